// round 3
// baseline (speedup 1.0000x reference)
#include <cuda_runtime.h>
#include <cuda_bf16.h>
#include <math.h>

// Problem constants
#define Bb   2
#define Ss   2048
#define Dd   2048
#define Hh   16
#define KVh  4
#define HD   128
#define Mrows (Bb*Ss)          // 4096

// ---------------- scratch (device globals; no allocation) ----------------
__device__ float g_Cq[Mrows * (Hh*HD)];     // 4096 x 2048
__device__ float g_Ck[Mrows * (KVh*HD)];    // 4096 x 512
__device__ float g_Cv[Mrows * (KVh*HD)];    // 4096 x 512
__device__ float g_Q [Bb*Hh *Ss*HD];        // (B,H,S,HD)
__device__ float g_K [Bb*KVh*Ss*HD];        // (B,KV,S,HD)
__device__ float g_V [Bb*KVh*Ss*HD];
__device__ float g_attn[Mrows * (Hh*HD)];   // (B,S,H,HD) flat 4096 x 2048

// =====================================================================
// SGEMM: C(MxN) = A(MxK) @ B(KxN), row-major, 128x128x8 tile, 256 thr,
// 8x8 register micro-tile per thread. M%128==0, N%128==0, K%8==0.
// =====================================================================
__global__ __launch_bounds__(256)
void sgemm_kernel(const float* __restrict__ A, const float* __restrict__ B,
                  float* __restrict__ C, int M, int N, int K)
{
    __shared__ float As[8][128];
    __shared__ float Bs[8][128];

    const int tid = threadIdx.x;
    const int bm = blockIdx.y * 128;
    const int bn = blockIdx.x * 128;
    const int ty = tid >> 4, tx = tid & 15;

    const int ar = tid >> 1;
    const int ak = (tid & 1) << 2;
    const int br = tid >> 5;
    const int bc = (tid & 31) << 2;

    float acc[8][8];
#pragma unroll
    for (int i = 0; i < 8; i++)
#pragma unroll
        for (int j = 0; j < 8; j++) acc[i][j] = 0.f;

    const float* Aptr = A + (size_t)(bm + ar) * K + ak;
    const float* Bptr = B + (size_t)br * N + bn + bc;

    for (int k0 = 0; k0 < K; k0 += 8) {
        float4 a  = *(const float4*)(Aptr + k0);
        float4 bv = *(const float4*)(Bptr + (size_t)k0 * N);
        As[ak + 0][ar] = a.x;
        As[ak + 1][ar] = a.y;
        As[ak + 2][ar] = a.z;
        As[ak + 3][ar] = a.w;
        *(float4*)&Bs[br][bc] = bv;
        __syncthreads();

#pragma unroll
        for (int kk = 0; kk < 8; kk++) {
            float av[8], bw[8];
            *(float4*)&av[0] = *(const float4*)&As[kk][ty * 8];
            *(float4*)&av[4] = *(const float4*)&As[kk][ty * 8 + 4];
            *(float4*)&bw[0] = *(const float4*)&Bs[kk][tx * 8];
            *(float4*)&bw[4] = *(const float4*)&Bs[kk][tx * 8 + 4];
#pragma unroll
            for (int i = 0; i < 8; i++)
#pragma unroll
                for (int j = 0; j < 8; j++)
                    acc[i][j] = fmaf(av[i], bw[j], acc[i][j]);
        }
        __syncthreads();
    }

#pragma unroll
    for (int i = 0; i < 8; i++) {
        float* crow = C + (size_t)(bm + ty * 8 + i) * N + bn + tx * 8;
        *(float4*)&crow[0] = make_float4(acc[i][0], acc[i][1], acc[i][2], acc[i][3]);
        *(float4*)&crow[4] = make_float4(acc[i][4], acc[i][5], acc[i][6], acc[i][7]);
    }
}

// =====================================================================
// Fused RoPE + transpose. One block per (s, b), 256 threads.
// cos/sin computed once per block in fp64. Completely different
// decomposition from the previous rope kernels (bisection experiment).
//   Cq (B*S, 16*128) -> Q (B,16,S,128) rotated
//   Ck (B*S, 4*128)  -> K (B,4,S,128)  rotated
//   Cv (B*S, 4*128)  -> V (B,4,S,128)  copied
// out[i]    = x[i]*cos_i   - x[i+64]*sin_i     (i < 64)
// out[i+64] = x[i+64]*cos_i + x[i]*sin_i
// inv_freq_i = 10000^(-i/64)
// =====================================================================
__global__ __launch_bounds__(256)
void rope_all_kernel(const float* __restrict__ Cq, const float* __restrict__ Ck,
                     const float* __restrict__ Cv,
                     float* __restrict__ Q, float* __restrict__ K,
                     float* __restrict__ V)
{
    __shared__ float cs[64], sn[64];
    const int s = blockIdx.x, b = blockIdx.y;
    const int tid = threadIdx.x;

    if (tid < 64) {
        double f = pow(10000.0, -(double)tid / 64.0);
        double a = (double)s * f;
        cs[tid] = (float)cos(a);
        sn[tid] = (float)sin(a);
    }
    __syncthreads();

    // Q: 16 heads x 64 rotation pairs
    const float* cq = Cq + (size_t)(b * Ss + s) * (Hh * HD);
    for (int p = tid; p < Hh * 64; p += 256) {
        int u = p >> 6, i = p & 63;
        float x1 = cq[u * HD + i], x2 = cq[u * HD + i + 64];
        float c = cs[i], sv = sn[i];
        float* dst = Q + ((size_t)(b * Hh + u) * Ss + s) * HD;
        dst[i]      = x1 * c - x2 * sv;
        dst[i + 64] = x2 * c + x1 * sv;
    }

    // K: 4 heads x 64 rotation pairs
    const float* ck = Ck + (size_t)(b * Ss + s) * (KVh * HD);
    for (int p = tid; p < KVh * 64; p += 256) {
        int u = p >> 6, i = p & 63;
        float x1 = ck[u * HD + i], x2 = ck[u * HD + i + 64];
        float c = cs[i], sv = sn[i];
        float* dst = K + ((size_t)(b * KVh + u) * Ss + s) * HD;
        dst[i]      = x1 * c - x2 * sv;
        dst[i + 64] = x2 * c + x1 * sv;
    }

    // V: 4 heads x 128 copies
    const float* cv = Cv + (size_t)(b * Ss + s) * (KVh * HD);
    for (int p = tid; p < KVh * HD; p += 256) {
        int u = p >> 7, d = p & 127;
        V[((size_t)(b * KVh + u) * Ss + s) * HD + d] = cv[u * HD + d];
    }
}

// =====================================================================
// SIMPLE attention (verification-grade). One block per (q-row, head, b).
// Two-pass softmax with full score row in shared memory. Causal.
// =====================================================================
__global__ __launch_bounds__(256)
void attn_simple_kernel(const float* __restrict__ Q, const float* __restrict__ K,
                        const float* __restrict__ V, float* __restrict__ O)
{
    __shared__ float sc[Ss];     // score row (up to 2048 keys)
    __shared__ float red[256];
    __shared__ float qr[HD];

    const int s = blockIdx.x, u = blockIdx.y, b = blockIdx.z;
    const int tid = threadIdx.x;
    const int nk = s + 1;        // causal: keys 0..s

    const float* qg = Q + ((size_t)(b * Hh + u) * Ss + s) * HD;
    const float* Kg = K + (size_t)(b * KVh + (u >> 2)) * Ss * HD;
    const float* Vg = V + (size_t)(b * KVh + (u >> 2)) * Ss * HD;

    if (tid < HD) qr[tid] = qg[tid];
    __syncthreads();

    const float scale = 0.08838834764831845f;   // 1/sqrt(128)

    // scores
    for (int k = tid; k < nk; k += 256) {
        const float4* kr = (const float4*)(Kg + (size_t)k * HD);
        float dot = 0.f;
#pragma unroll
        for (int d4 = 0; d4 < 32; d4++) {
            float4 kv = kr[d4];
            const float* q4 = qr + d4 * 4;
            dot += kv.x * q4[0] + kv.y * q4[1] + kv.z * q4[2] + kv.w * q4[3];
        }
        sc[k] = dot * scale;
    }
    __syncthreads();

    // max reduce
    float mx = -1e30f;
    for (int k = tid; k < nk; k += 256) mx = fmaxf(mx, sc[k]);
    red[tid] = mx;
    __syncthreads();
    for (int off = 128; off > 0; off >>= 1) {
        if (tid < off) red[tid] = fmaxf(red[tid], red[tid + off]);
        __syncthreads();
    }
    mx = red[0];
    __syncthreads();

    // exp + sum reduce
    float ls = 0.f;
    for (int k = tid; k < nk; k += 256) {
        float p = __expf(sc[k] - mx);
        sc[k] = p;
        ls += p;
    }
    red[tid] = ls;
    __syncthreads();
    for (int off = 128; off > 0; off >>= 1) {
        if (tid < off) red[tid] += red[tid + off];
        __syncthreads();
    }
    const float inv = 1.f / red[0];
    __syncthreads();

    // PV: 2 threads per output dim (split keys by parity)
    const int d = tid & 127;
    const int half = tid >> 7;
    float acc = 0.f;
    for (int k = half; k < nk; k += 2)
        acc += sc[k] * Vg[(size_t)k * HD + d];
    red[tid] = acc;
    __syncthreads();
    if (tid < 128)
        O[((size_t)(b * Ss + s) * Hh + u) * HD + tid] =
            (red[tid] + red[tid + 128]) * inv;
}

// =====================================================================
// launch — input mapping robust to group ordering via in_sizes pattern.
// Groups: 8388608 = {hidden_states, attention_mask} (hidden first),
//         4194304 = {Wq, Wo} (Wq first), 1048576 = {Wk, Wv} (Wk first).
// =====================================================================
extern "C" void kernel_launch(void* const* d_in, const int* in_sizes, int n_in,
                              void* d_out, int out_size)
{
    const float *X = 0, *Wq = 0, *Wk = 0, *Wv = 0, *Wo = 0;
    int seen_big = 0, seen_mid = 0, seen_small = 0;
    for (int i = 0; i < n_in; i++) {
        long sz = in_sizes[i];
        if (sz == 8388608) {            // hidden_states then attention_mask
            if (seen_big == 0) X = (const float*)d_in[i];
            seen_big++;
        } else if (sz == 4194304) {     // Wq then Wo
            if (seen_mid == 0) Wq = (const float*)d_in[i];
            else               Wo = (const float*)d_in[i];
            seen_mid++;
        } else if (sz == 1048576) {     // Wk then Wv
            if (seen_small == 0) Wk = (const float*)d_in[i];
            else                 Wv = (const float*)d_in[i];
            seen_small++;
        }
    }
    // fallback to dict order if pattern unexpected
    if (!X || !Wq || !Wk || !Wv || !Wo) {
        X  = (const float*)d_in[0];
        Wq = (const float*)d_in[2];
        Wk = (const float*)d_in[3];
        Wv = (const float*)d_in[4];
        Wo = (const float*)d_in[5];
    }
    float* out = (float*)d_out;

    float *Cq, *Ck, *Cv, *Qp, *Kp, *Vp, *attn;
    cudaGetSymbolAddress((void**)&Cq,   g_Cq);
    cudaGetSymbolAddress((void**)&Ck,   g_Ck);
    cudaGetSymbolAddress((void**)&Cv,   g_Cv);
    cudaGetSymbolAddress((void**)&Qp,   g_Q);
    cudaGetSymbolAddress((void**)&Kp,   g_K);
    cudaGetSymbolAddress((void**)&Vp,   g_V);
    cudaGetSymbolAddress((void**)&attn, g_attn);

    // QKV projections
    sgemm_kernel<<<dim3(2048 / 128, Mrows / 128), 256>>>(X, Wq, Cq, Mrows, 2048, 2048);
    sgemm_kernel<<<dim3(512 / 128,  Mrows / 128), 256>>>(X, Wk, Ck, Mrows, 512, 2048);
    sgemm_kernel<<<dim3(512 / 128,  Mrows / 128), 256>>>(X, Wv, Cv, Mrows, 512, 2048);

    // Fused RoPE + transpose (new decomposition, fp64 angles)
    rope_all_kernel<<<dim3(Ss, Bb), 256>>>(Cq, Ck, Cv, Qp, Kp, Vp);

    // Attention (simple, verification-grade)
    attn_simple_kernel<<<dim3(Ss, Hh, Bb), 256>>>(Qp, Kp, Vp, attn);

    // Output projection: attn (4096x2048) @ Wo-flat (2048x2048) -> out
    sgemm_kernel<<<dim3(2048 / 128, Mrows / 128), 256>>>(attn, Wo, out, Mrows, 2048, 2048);
}

// round 4
// speedup vs baseline: 3.3659x; 3.3659x over previous
#include <cuda_runtime.h>
#include <cuda_bf16.h>
#include <math.h>

// Problem constants
#define Bb   2
#define Ss   2048
#define Dd   2048
#define Hh   16
#define KVh  4
#define HD   128
#define Mrows (Bb*Ss)          // 4096

// ---------------- scratch (device globals; no allocation) ----------------
__device__ float g_Cq[Mrows * (Hh*HD)];     // 4096 x 2048
__device__ float g_Ck[Mrows * (KVh*HD)];    // 4096 x 512
__device__ float g_Cv[Mrows * (KVh*HD)];    // 4096 x 512
__device__ float g_Q [Bb*Hh *Ss*HD];        // (B,H,S,HD)
__device__ float g_K [Bb*KVh*Ss*HD];        // (B,KV,S,HD)
__device__ float g_V [Bb*KVh*Ss*HD];
__device__ float g_attn[Mrows * (Hh*HD)];   // (B,S,H,HD) flat 4096 x 2048

// =====================================================================
// SGEMM: C(MxN) = A(MxK) @ B(KxN), row-major, 128x128x8 tile, 256 thr,
// 8x8 register micro-tile per thread. M%128==0, N%128==0, K%8==0.
// =====================================================================
__global__ __launch_bounds__(256)
void sgemm_kernel(const float* __restrict__ A, const float* __restrict__ B,
                  float* __restrict__ C, int M, int N, int K)
{
    __shared__ float As[8][128];
    __shared__ float Bs[8][128];

    const int tid = threadIdx.x;
    const int bm = blockIdx.y * 128;
    const int bn = blockIdx.x * 128;
    const int ty = tid >> 4, tx = tid & 15;

    const int ar = tid >> 1;
    const int ak = (tid & 1) << 2;
    const int br = tid >> 5;
    const int bc = (tid & 31) << 2;

    float acc[8][8];
#pragma unroll
    for (int i = 0; i < 8; i++)
#pragma unroll
        for (int j = 0; j < 8; j++) acc[i][j] = 0.f;

    const float* Aptr = A + (size_t)(bm + ar) * K + ak;
    const float* Bptr = B + (size_t)br * N + bn + bc;

    for (int k0 = 0; k0 < K; k0 += 8) {
        float4 a  = *(const float4*)(Aptr + k0);
        float4 bv = *(const float4*)(Bptr + (size_t)k0 * N);
        As[ak + 0][ar] = a.x;
        As[ak + 1][ar] = a.y;
        As[ak + 2][ar] = a.z;
        As[ak + 3][ar] = a.w;
        *(float4*)&Bs[br][bc] = bv;
        __syncthreads();

#pragma unroll
        for (int kk = 0; kk < 8; kk++) {
            float av[8], bw[8];
            *(float4*)&av[0] = *(const float4*)&As[kk][ty * 8];
            *(float4*)&av[4] = *(const float4*)&As[kk][ty * 8 + 4];
            *(float4*)&bw[0] = *(const float4*)&Bs[kk][tx * 8];
            *(float4*)&bw[4] = *(const float4*)&Bs[kk][tx * 8 + 4];
#pragma unroll
            for (int i = 0; i < 8; i++)
#pragma unroll
                for (int j = 0; j < 8; j++)
                    acc[i][j] = fmaf(av[i], bw[j], acc[i][j]);
        }
        __syncthreads();
    }

#pragma unroll
    for (int i = 0; i < 8; i++) {
        float* crow = C + (size_t)(bm + ty * 8 + i) * N + bn + tx * 8;
        *(float4*)&crow[0] = make_float4(acc[i][0], acc[i][1], acc[i][2], acc[i][3]);
        *(float4*)&crow[4] = make_float4(acc[i][4], acc[i][5], acc[i][6], acc[i][7]);
    }
}

// =====================================================================
// Fused RoPE + transpose. One block per (s, b), 256 threads.
// cos/sin computed once per block in fp64.
// =====================================================================
__global__ __launch_bounds__(256)
void rope_all_kernel(const float* __restrict__ Cq, const float* __restrict__ Ck,
                     const float* __restrict__ Cv,
                     float* __restrict__ Q, float* __restrict__ K,
                     float* __restrict__ V)
{
    __shared__ float cs[64], sn[64];
    const int s = blockIdx.x, b = blockIdx.y;
    const int tid = threadIdx.x;

    if (tid < 64) {
        double f = pow(10000.0, -(double)tid / 64.0);
        double a = (double)s * f;
        cs[tid] = (float)cos(a);
        sn[tid] = (float)sin(a);
    }
    __syncthreads();

    // Q: 16 heads x 64 rotation pairs
    const float* cq = Cq + (size_t)(b * Ss + s) * (Hh * HD);
    for (int p = tid; p < Hh * 64; p += 256) {
        int u = p >> 6, i = p & 63;
        float x1 = cq[u * HD + i], x2 = cq[u * HD + i + 64];
        float c = cs[i], sv = sn[i];
        float* dst = Q + ((size_t)(b * Hh + u) * Ss + s) * HD;
        dst[i]      = x1 * c - x2 * sv;
        dst[i + 64] = x2 * c + x1 * sv;
    }

    // K: 4 heads x 64 rotation pairs
    const float* ck = Ck + (size_t)(b * Ss + s) * (KVh * HD);
    for (int p = tid; p < KVh * 64; p += 256) {
        int u = p >> 6, i = p & 63;
        float x1 = ck[u * HD + i], x2 = ck[u * HD + i + 64];
        float c = cs[i], sv = sn[i];
        float* dst = K + ((size_t)(b * KVh + u) * Ss + s) * HD;
        dst[i]      = x1 * c - x2 * sv;
        dst[i + 64] = x2 * c + x1 * sv;
    }

    // V: 4 heads x 128 copies
    const float* cv = Cv + (size_t)(b * Ss + s) * (KVh * HD);
    for (int p = tid; p < KVh * HD; p += 256) {
        int u = p >> 7, d = p & 127;
        V[((size_t)(b * KVh + u) * Ss + s) * HD + d] = cv[u * HD + d];
    }
}

// =====================================================================
// Flash attention (causal, GQA). BQ=BK=64, HD=128, fp32, online softmax.
// grid (S/64, H, B), 256 threads. Output layout (B,S,H,HD).
// =====================================================================
#define ATTN_SMEM_FLOATS (64*128 + 64*128 + 64*129 + 64*65 + 3*64)
#define ATTN_SMEM_BYTES  (ATTN_SMEM_FLOATS * 4)

__global__ __launch_bounds__(256)
void attn_kernel(const float* __restrict__ Q, const float* __restrict__ K,
                 const float* __restrict__ V, float* __restrict__ O)
{
    extern __shared__ float sm[];
    float* Qs  = sm;                   // [64][128]
    float* Vs  = Qs + 64 * 128;        // [64][128]
    float* Ks  = Vs + 64 * 128;        // [64][129]
    float* Ps  = Ks + 64 * 129;        // [64][65]
    float* m_s = Ps + 64 * 65;         // [64]
    float* l_s = m_s + 64;             // [64]
    float* sc_s = l_s + 64;            // [64]

    const int qt = blockIdx.x, u = blockIdx.y, b = blockIdx.z;
    const int tid = threadIdx.x;
    const int ty = tid >> 4, tx = tid & 15;
    const int r0 = ty * 4;             // 4 score/output rows
    const int c0 = tx * 4;             // 4 score cols
    const int cc = tx * 8;             // 8 output cols

    const float* Qg = Q + ((size_t)(b * Hh + u) * Ss + qt * 64) * HD;
    const float* Kg = K + (size_t)(b * KVh + (u >> 2)) * Ss * HD;
    const float* Vg = V + (size_t)(b * KVh + (u >> 2)) * Ss * HD;

    // load Q tile
    for (int e = tid; e < 64 * 32; e += 256) {
        int r = e >> 5, c4 = (e & 31) << 2;
        *(float4*)&Qs[r * 128 + c4] = *(const float4*)&Qg[r * 128 + c4];
    }
    if (tid < 64) { m_s[tid] = -1e30f; l_s[tid] = 0.f; }

    float acc[4][8];
#pragma unroll
    for (int i = 0; i < 4; i++)
#pragma unroll
        for (int j = 0; j < 8; j++) acc[i][j] = 0.f;

    __syncthreads();

    const float sscale = 0.08838834764831845f;   // 1/sqrt(128)

    for (int kt = 0; kt <= qt; kt++) {
        const float* kg = Kg + (size_t)kt * 64 * HD;
        const float* vg = Vg + (size_t)kt * 64 * HD;
        for (int e = tid; e < 64 * 32; e += 256) {
            int r = e >> 5, c4 = (e & 31) << 2;
            float4 kv = *(const float4*)&kg[r * 128 + c4];
            Ks[r * 129 + c4 + 0] = kv.x;
            Ks[r * 129 + c4 + 1] = kv.y;
            Ks[r * 129 + c4 + 2] = kv.z;
            Ks[r * 129 + c4 + 3] = kv.w;
            *(float4*)&Vs[r * 128 + c4] = *(const float4*)&vg[r * 128 + c4];
        }
        __syncthreads();

        // S = Q K^T  (4x4 per thread)
        float s4[4][4];
#pragma unroll
        for (int i = 0; i < 4; i++)
#pragma unroll
            for (int j = 0; j < 4; j++) s4[i][j] = 0.f;

#pragma unroll 4
        for (int d = 0; d < 128; d++) {
            float qv[4], kv[4];
#pragma unroll
            for (int i = 0; i < 4; i++) qv[i] = Qs[(r0 + i) * 128 + d];
#pragma unroll
            for (int j = 0; j < 4; j++) kv[j] = Ks[(c0 + j) * 129 + d];
#pragma unroll
            for (int i = 0; i < 4; i++)
#pragma unroll
                for (int j = 0; j < 4; j++)
                    s4[i][j] = fmaf(qv[i], kv[j], s4[i][j]);
        }

        const bool diag = (kt == qt);
#pragma unroll
        for (int i = 0; i < 4; i++)
#pragma unroll
            for (int j = 0; j < 4; j++) {
                float val = s4[i][j] * sscale;
                if (diag && (c0 + j > r0 + i)) val = -1e30f;
                Ps[(r0 + i) * 65 + (c0 + j)] = val;
            }
        __syncthreads();

        // online softmax update, one thread per row
        if (tid < 64) {
            float* prow = Ps + tid * 65;
            float mold = m_s[tid];
            float mx = mold;
#pragma unroll 8
            for (int c = 0; c < 64; c++) mx = fmaxf(mx, prow[c]);
            float lsum = 0.f;
#pragma unroll 8
            for (int c = 0; c < 64; c++) {
                float p = __expf(prow[c] - mx);
                prow[c] = p;
                lsum += p;
            }
            float so = __expf(mold - mx);
            sc_s[tid] = so;
            m_s[tid] = mx;
            l_s[tid] = l_s[tid] * so + lsum;
        }
        __syncthreads();

        // O = O*scale + P@V  (4 rows x 8 cols per thread)
#pragma unroll
        for (int i = 0; i < 4; i++) {
            float sc = sc_s[r0 + i];
#pragma unroll
            for (int j = 0; j < 8; j++) acc[i][j] *= sc;
        }
#pragma unroll 2
        for (int c = 0; c < 64; c++) {
            float p0 = Ps[(r0 + 0) * 65 + c];
            float p1 = Ps[(r0 + 1) * 65 + c];
            float p2 = Ps[(r0 + 2) * 65 + c];
            float p3 = Ps[(r0 + 3) * 65 + c];
            float4 va = *(const float4*)&Vs[c * 128 + cc];
            float4 vb = *(const float4*)&Vs[c * 128 + cc + 4];
            acc[0][0] = fmaf(p0, va.x, acc[0][0]);
            acc[0][1] = fmaf(p0, va.y, acc[0][1]);
            acc[0][2] = fmaf(p0, va.z, acc[0][2]);
            acc[0][3] = fmaf(p0, va.w, acc[0][3]);
            acc[0][4] = fmaf(p0, vb.x, acc[0][4]);
            acc[0][5] = fmaf(p0, vb.y, acc[0][5]);
            acc[0][6] = fmaf(p0, vb.z, acc[0][6]);
            acc[0][7] = fmaf(p0, vb.w, acc[0][7]);
            acc[1][0] = fmaf(p1, va.x, acc[1][0]);
            acc[1][1] = fmaf(p1, va.y, acc[1][1]);
            acc[1][2] = fmaf(p1, va.z, acc[1][2]);
            acc[1][3] = fmaf(p1, va.w, acc[1][3]);
            acc[1][4] = fmaf(p1, vb.x, acc[1][4]);
            acc[1][5] = fmaf(p1, vb.y, acc[1][5]);
            acc[1][6] = fmaf(p1, vb.z, acc[1][6]);
            acc[1][7] = fmaf(p1, vb.w, acc[1][7]);
            acc[2][0] = fmaf(p2, va.x, acc[2][0]);
            acc[2][1] = fmaf(p2, va.y, acc[2][1]);
            acc[2][2] = fmaf(p2, va.z, acc[2][2]);
            acc[2][3] = fmaf(p2, va.w, acc[2][3]);
            acc[2][4] = fmaf(p2, vb.x, acc[2][4]);
            acc[2][5] = fmaf(p2, vb.y, acc[2][5]);
            acc[2][6] = fmaf(p2, vb.z, acc[2][6]);
            acc[2][7] = fmaf(p2, vb.w, acc[2][7]);
            acc[3][0] = fmaf(p3, va.x, acc[3][0]);
            acc[3][1] = fmaf(p3, va.y, acc[3][1]);
            acc[3][2] = fmaf(p3, va.z, acc[3][2]);
            acc[3][3] = fmaf(p3, va.w, acc[3][3]);
            acc[3][4] = fmaf(p3, vb.x, acc[3][4]);
            acc[3][5] = fmaf(p3, vb.y, acc[3][5]);
            acc[3][6] = fmaf(p3, vb.z, acc[3][6]);
            acc[3][7] = fmaf(p3, vb.w, acc[3][7]);
        }
        __syncthreads();
    }

    // epilogue: divide by l, write (B,S,H,HD)
#pragma unroll
    for (int i = 0; i < 4; i++) {
        float inv = 1.f / l_s[r0 + i];
        int sg = qt * 64 + r0 + i;
        float* og = O + ((size_t)(b * Ss + sg) * Hh + u) * HD + cc;
        *(float4*)&og[0] = make_float4(acc[i][0] * inv, acc[i][1] * inv,
                                       acc[i][2] * inv, acc[i][3] * inv);
        *(float4*)&og[4] = make_float4(acc[i][4] * inv, acc[i][5] * inv,
                                       acc[i][6] * inv, acc[i][7] * inv);
    }
}

// =====================================================================
// launch
// =====================================================================
extern "C" void kernel_launch(void* const* d_in, const int* in_sizes, int n_in,
                              void* d_out, int out_size)
{
    const float *X = 0, *Wq = 0, *Wk = 0, *Wv = 0, *Wo = 0;
    int seen_big = 0, seen_mid = 0, seen_small = 0;
    for (int i = 0; i < n_in; i++) {
        long sz = in_sizes[i];
        if (sz == 8388608) {            // hidden_states then attention_mask
            if (seen_big == 0) X = (const float*)d_in[i];
            seen_big++;
        } else if (sz == 4194304) {     // Wq then Wo
            if (seen_mid == 0) Wq = (const float*)d_in[i];
            else               Wo = (const float*)d_in[i];
            seen_mid++;
        } else if (sz == 1048576) {     // Wk then Wv
            if (seen_small == 0) Wk = (const float*)d_in[i];
            else                 Wv = (const float*)d_in[i];
            seen_small++;
        }
    }
    if (!X || !Wq || !Wk || !Wv || !Wo) {
        X  = (const float*)d_in[0];
        Wq = (const float*)d_in[2];
        Wk = (const float*)d_in[3];
        Wv = (const float*)d_in[4];
        Wo = (const float*)d_in[5];
    }
    float* out = (float*)d_out;

    float *Cq, *Ck, *Cv, *Qp, *Kp, *Vp, *attn;
    cudaGetSymbolAddress((void**)&Cq,   g_Cq);
    cudaGetSymbolAddress((void**)&Ck,   g_Ck);
    cudaGetSymbolAddress((void**)&Cv,   g_Cv);
    cudaGetSymbolAddress((void**)&Qp,   g_Q);
    cudaGetSymbolAddress((void**)&Kp,   g_K);
    cudaGetSymbolAddress((void**)&Vp,   g_V);
    cudaGetSymbolAddress((void**)&attn, g_attn);

    // QKV projections
    sgemm_kernel<<<dim3(2048 / 128, Mrows / 128), 256>>>(X, Wq, Cq, Mrows, 2048, 2048);
    sgemm_kernel<<<dim3(512 / 128,  Mrows / 128), 256>>>(X, Wk, Ck, Mrows, 512, 2048);
    sgemm_kernel<<<dim3(512 / 128,  Mrows / 128), 256>>>(X, Wv, Cv, Mrows, 512, 2048);

    // Fused RoPE + transpose
    rope_all_kernel<<<dim3(Ss, Bb), 256>>>(Cq, Ck, Cv, Qp, Kp, Vp);

    // Flash attention
    cudaFuncSetAttribute(attn_kernel, cudaFuncAttributeMaxDynamicSharedMemorySize,
                         ATTN_SMEM_BYTES);
    attn_kernel<<<dim3(Ss / 64, Hh, Bb), 256, ATTN_SMEM_BYTES>>>(Qp, Kp, Vp, attn);

    // Output projection: attn (4096x2048) @ Wo-flat (2048x2048) -> out
    sgemm_kernel<<<dim3(2048 / 128, Mrows / 128), 256>>>(attn, Wo, out, Mrows, 2048, 2048);
}

// round 5
// speedup vs baseline: 5.5459x; 1.6476x over previous
#include <cuda_runtime.h>
#include <cuda_bf16.h>
#include <math.h>
#include <stdint.h>

// Problem constants
#define Bb   2
#define Ss   2048
#define Dd   2048
#define Hh   16
#define KVh  4
#define HD   128
#define Mrows (Bb*Ss)          // 4096

// ---------------- scratch (device globals; no allocation) ----------------
__device__ float g_Cq[Mrows * (Hh*HD)];     // 4096 x 2048
__device__ float g_Ck[Mrows * (KVh*HD)];    // 4096 x 512
__device__ float g_Cv[Mrows * (KVh*HD)];    // 4096 x 512
__device__ float g_Q [Bb*Hh *Ss*HD];        // (B,H,S,HD)
__device__ float g_K [Bb*KVh*Ss*HD];        // (B,KV,S,HD)
__device__ float g_V [Bb*KVh*Ss*HD];
__device__ float g_attn[Mrows * (Hh*HD)];   // (B,S,H,HD) flat 4096 x 2048

// bf16 hi/lo split operands
__device__ __nv_bfloat16 g_Xh[Mrows*Dd],  g_Xl[Mrows*Dd];        // X  [M][K]
__device__ __nv_bfloat16 g_Ath[Mrows*Dd], g_Atl[Mrows*Dd];       // attn [M][K]
__device__ __nv_bfloat16 g_Wqh[Dd*Dd],    g_Wql[Dd*Dd];          // Wq^T [N][K]
__device__ __nv_bfloat16 g_Wkh[512*Dd],   g_Wkl[512*Dd];         // Wk^T
__device__ __nv_bfloat16 g_Wvh[512*Dd],   g_Wvl[512*Dd];         // Wv^T
__device__ __nv_bfloat16 g_Woh[Dd*Dd],    g_Wol[Dd*Dd];          // Wo^T

// =====================================================================
// cp.async helpers
// =====================================================================
#define CP_ASYNC16(daddr, gptr) \
    asm volatile("cp.async.cg.shared.global [%0], [%1], 16;\n" :: "r"(daddr), "l"(gptr))
#define CP_COMMIT()  asm volatile("cp.async.commit_group;\n" ::)
#define CP_WAIT(n)   asm volatile("cp.async.wait_group %0;\n" :: "n"(n))

#define MMA_BF16(d, a, b) \
    asm volatile("mma.sync.aligned.m16n8k16.row.col.f32.bf16.bf16.f32 " \
        "{%0,%1,%2,%3}, {%4,%5,%6,%7}, {%8,%9}, {%0,%1,%2,%3};\n" \
        : "+f"(d[0]), "+f"(d[1]), "+f"(d[2]), "+f"(d[3]) \
        : "r"(a[0]), "r"(a[1]), "r"(a[2]), "r"(a[3]), "r"(b[0]), "r"(b[1]))

// =====================================================================
// split: fp32 -> bf16 hi + bf16 lo (lo = bf16(x - hi)), float4 per thread
// =====================================================================
__global__ __launch_bounds__(256)
void split_kernel(const float* __restrict__ in, __nv_bfloat16* __restrict__ hi,
                  __nv_bfloat16* __restrict__ lo, int n4)
{
    int i = blockIdx.x * 256 + threadIdx.x;
    if (i >= n4) return;
    float4 x = ((const float4*)in)[i];
    __nv_bfloat16 h0 = __float2bfloat16(x.x), h1 = __float2bfloat16(x.y);
    __nv_bfloat16 h2 = __float2bfloat16(x.z), h3 = __float2bfloat16(x.w);
    __nv_bfloat16 l0 = __float2bfloat16(x.x - __bfloat162float(h0));
    __nv_bfloat16 l1 = __float2bfloat16(x.y - __bfloat162float(h1));
    __nv_bfloat16 l2 = __float2bfloat16(x.z - __bfloat162float(h2));
    __nv_bfloat16 l3 = __float2bfloat16(x.w - __bfloat162float(h3));
    ((__nv_bfloat162*)hi)[i*2]   = __nv_bfloat162(h0, h1);
    ((__nv_bfloat162*)hi)[i*2+1] = __nv_bfloat162(h2, h3);
    ((__nv_bfloat162*)lo)[i*2]   = __nv_bfloat162(l0, l1);
    ((__nv_bfloat162*)lo)[i*2+1] = __nv_bfloat162(l2, l3);
}

// =====================================================================
// split + transpose: W [K][N] fp32 -> Th/Tl [N][K] bf16
// =====================================================================
__global__ __launch_bounds__(256)
void split_t_kernel(const float* __restrict__ W, __nv_bfloat16* __restrict__ Th,
                    __nv_bfloat16* __restrict__ Tl, int K, int N)
{
    __shared__ float t[32][33];
    const int nb = blockIdx.x * 32, kb = blockIdx.y * 32;
    const int tx = threadIdx.x, ty = threadIdx.y;   // 32 x 8
#pragma unroll
    for (int i = 0; i < 32; i += 8)
        t[ty + i][tx] = W[(size_t)(kb + ty + i) * N + nb + tx];
    __syncthreads();
#pragma unroll
    for (int i = 0; i < 32; i += 8) {
        float x = t[tx][ty + i];
        __nv_bfloat16 h = __float2bfloat16(x);
        size_t o = (size_t)(nb + ty + i) * K + kb + tx;
        Th[o] = h;
        Tl[o] = __float2bfloat16(x - __bfloat162float(h));
    }
}

// =====================================================================
// GEMM (bf16x3): C[M][N] fp32 = (Ah+Al)[M][K] @ (Bh+Bl)[N][K]^T
// CTA 128x128, 8 warps (2m x 4n, warp tile 64x32), K-chunk 32,
// cp.async double buffer. smem stride 40 halves (conflict-free frags).
// =====================================================================
#define GPL 5120            // plane: 128 rows * 40 halves
#define GEMM_SMEM (2*2*2*GPL*2)   // mats*bufs*parts*plane*2B = 81920

__device__ __forceinline__ void gemm_fill(
    const __nv_bfloat16* Ah, const __nv_bfloat16* Al,
    const __nv_bfloat16* Bh, const __nv_bfloat16* Bl,
    int K, int m0, int n0, int k0, uint32_t sbase, int buf, int tid)
{
#pragma unroll
    for (int j = 0; j < 8; j++) {
        int e = tid + j * 256;
        int mat = e >> 10, part = (e >> 9) & 1, idx = e & 511;
        int row = idx >> 2, seg = idx & 3;
        const __nv_bfloat16* g;
        if (mat == 0) g = (part ? Al : Ah) + (size_t)(m0 + row) * K + k0 + seg * 8;
        else          g = (part ? Bl : Bh) + (size_t)(n0 + row) * K + k0 + seg * 8;
        uint32_t daddr = sbase +
            (uint32_t)((((mat * 2 + buf) * 2 + part) * GPL + row * 40 + seg * 8) * 2);
        CP_ASYNC16(daddr, g);
    }
}

__global__ __launch_bounds__(256)
void gemm_bf16x3(const __nv_bfloat16* __restrict__ Ah, const __nv_bfloat16* __restrict__ Al,
                 const __nv_bfloat16* __restrict__ Bh, const __nv_bfloat16* __restrict__ Bl,
                 float* __restrict__ C, int M, int N, int K)
{
    extern __shared__ __nv_bfloat16 smg[];
    const int tid = threadIdx.x;
    const int m0 = blockIdx.y * 128, n0 = blockIdx.x * 128;
    const int warp = tid >> 5, lane = tid & 31;
    const int g = lane >> 2, ctg = lane & 3;
    const int wm = (warp >> 2) * 64, wn = (warp & 3) * 32;
    const uint32_t sbase = (uint32_t)__cvta_generic_to_shared(smg);

    float acc[4][4][4];
#pragma unroll
    for (int a = 0; a < 4; a++)
#pragma unroll
        for (int b = 0; b < 4; b++)
#pragma unroll
            for (int c = 0; c < 4; c++) acc[a][b][c] = 0.f;

    const int nc = K / 32;
    gemm_fill(Ah, Al, Bh, Bl, K, m0, n0, 0, sbase, 0, tid);
    CP_COMMIT();

    for (int c = 0; c < nc; c++) {
        if (c + 1 < nc) {
            gemm_fill(Ah, Al, Bh, Bl, K, m0, n0, (c + 1) * 32, sbase, (c + 1) & 1, tid);
            CP_COMMIT();
            CP_WAIT(1);
        } else {
            CP_WAIT(0);
        }
        __syncthreads();

        const int buf = c & 1;
        const __nv_bfloat16* Ahs = smg + ((0 * 2 + buf) * 2 + 0) * GPL;
        const __nv_bfloat16* Als = smg + ((0 * 2 + buf) * 2 + 1) * GPL;
        const __nv_bfloat16* Bhs = smg + ((1 * 2 + buf) * 2 + 0) * GPL;
        const __nv_bfloat16* Bls = smg + ((1 * 2 + buf) * 2 + 1) * GPL;

#pragma unroll
        for (int kk = 0; kk < 32; kk += 16) {
            uint32_t ah[4][4], al[4][4], bh[4][2], bl[4][2];
#pragma unroll
            for (int mf = 0; mf < 4; mf++) {
                int o = (wm + mf * 16 + g) * 40 + kk + 2 * ctg;
                ah[mf][0] = *(const uint32_t*)&Ahs[o];
                ah[mf][1] = *(const uint32_t*)&Ahs[o + 8 * 40];
                ah[mf][2] = *(const uint32_t*)&Ahs[o + 8];
                ah[mf][3] = *(const uint32_t*)&Ahs[o + 8 * 40 + 8];
                al[mf][0] = *(const uint32_t*)&Als[o];
                al[mf][1] = *(const uint32_t*)&Als[o + 8 * 40];
                al[mf][2] = *(const uint32_t*)&Als[o + 8];
                al[mf][3] = *(const uint32_t*)&Als[o + 8 * 40 + 8];
            }
#pragma unroll
            for (int nf = 0; nf < 4; nf++) {
                int o = (wn + nf * 8 + g) * 40 + kk + 2 * ctg;
                bh[nf][0] = *(const uint32_t*)&Bhs[o];
                bh[nf][1] = *(const uint32_t*)&Bhs[o + 8];
                bl[nf][0] = *(const uint32_t*)&Bls[o];
                bl[nf][1] = *(const uint32_t*)&Bls[o + 8];
            }
#pragma unroll
            for (int mf = 0; mf < 4; mf++)
#pragma unroll
                for (int nf = 0; nf < 4; nf++) MMA_BF16(acc[mf][nf], ah[mf], bh[nf]);
#pragma unroll
            for (int mf = 0; mf < 4; mf++)
#pragma unroll
                for (int nf = 0; nf < 4; nf++) MMA_BF16(acc[mf][nf], ah[mf], bl[nf]);
#pragma unroll
            for (int mf = 0; mf < 4; mf++)
#pragma unroll
                for (int nf = 0; nf < 4; nf++) MMA_BF16(acc[mf][nf], al[mf], bh[nf]);
        }
        __syncthreads();
    }

    // epilogue
#pragma unroll
    for (int mf = 0; mf < 4; mf++)
#pragma unroll
        for (int nf = 0; nf < 4; nf++) {
            int r  = m0 + wm + mf * 16 + g;
            int cl = n0 + wn + nf * 8 + 2 * ctg;
            *(float2*)&C[(size_t)r * N + cl]       = make_float2(acc[mf][nf][0], acc[mf][nf][1]);
            *(float2*)&C[(size_t)(r + 8) * N + cl] = make_float2(acc[mf][nf][2], acc[mf][nf][3]);
        }
}

// =====================================================================
// Fused RoPE + transpose. One block per (s, b), 256 threads.
// =====================================================================
__global__ __launch_bounds__(256)
void rope_all_kernel(const float* __restrict__ Cq, const float* __restrict__ Ck,
                     const float* __restrict__ Cv,
                     float* __restrict__ Q, float* __restrict__ K,
                     float* __restrict__ V)
{
    __shared__ float cs[64], sn[64];
    const int s = blockIdx.x, b = blockIdx.y;
    const int tid = threadIdx.x;

    if (tid < 64) {
        double f = pow(10000.0, -(double)tid / 64.0);
        double a = (double)s * f;
        cs[tid] = (float)cos(a);
        sn[tid] = (float)sin(a);
    }
    __syncthreads();

    const float* cq = Cq + (size_t)(b * Ss + s) * (Hh * HD);
    for (int p = tid; p < Hh * 64; p += 256) {
        int u = p >> 6, i = p & 63;
        float x1 = cq[u * HD + i], x2 = cq[u * HD + i + 64];
        float c = cs[i], sv = sn[i];
        float* dst = Q + ((size_t)(b * Hh + u) * Ss + s) * HD;
        dst[i]      = x1 * c - x2 * sv;
        dst[i + 64] = x2 * c + x1 * sv;
    }

    const float* ck = Ck + (size_t)(b * Ss + s) * (KVh * HD);
    for (int p = tid; p < KVh * 64; p += 256) {
        int u = p >> 6, i = p & 63;
        float x1 = ck[u * HD + i], x2 = ck[u * HD + i + 64];
        float c = cs[i], sv = sn[i];
        float* dst = K + ((size_t)(b * KVh + u) * Ss + s) * HD;
        dst[i]      = x1 * c - x2 * sv;
        dst[i + 64] = x2 * c + x1 * sv;
    }

    const float* cv = Cv + (size_t)(b * Ss + s) * (KVh * HD);
    for (int p = tid; p < KVh * HD; p += 256) {
        int u = p >> 7, d = p & 127;
        V[((size_t)(b * KVh + u) * Ss + s) * HD + d] = cv[u * HD + d];
    }
}

// =====================================================================
// Flash attention (causal, GQA). BQ=BK=64, HD=128, fp32, online softmax.
// =====================================================================
#define ATTN_SMEM_FLOATS (64*128 + 64*128 + 64*129 + 64*65 + 3*64)
#define ATTN_SMEM_BYTES  (ATTN_SMEM_FLOATS * 4)

__global__ __launch_bounds__(256)
void attn_kernel(const float* __restrict__ Q, const float* __restrict__ K,
                 const float* __restrict__ V, float* __restrict__ O)
{
    extern __shared__ float sm[];
    float* Qs  = sm;
    float* Vs  = Qs + 64 * 128;
    float* Ks  = Vs + 64 * 128;
    float* Ps  = Ks + 64 * 129;
    float* m_s = Ps + 64 * 65;
    float* l_s = m_s + 64;
    float* sc_s = l_s + 64;

    const int qt = blockIdx.x, u = blockIdx.y, b = blockIdx.z;
    const int tid = threadIdx.x;
    const int ty = tid >> 4, tx = tid & 15;
    const int r0 = ty * 4;
    const int c0 = tx * 4;
    const int cc = tx * 8;

    const float* Qg = Q + ((size_t)(b * Hh + u) * Ss + qt * 64) * HD;
    const float* Kg = K + (size_t)(b * KVh + (u >> 2)) * Ss * HD;
    const float* Vg = V + (size_t)(b * KVh + (u >> 2)) * Ss * HD;

    for (int e = tid; e < 64 * 32; e += 256) {
        int r = e >> 5, c4 = (e & 31) << 2;
        *(float4*)&Qs[r * 128 + c4] = *(const float4*)&Qg[r * 128 + c4];
    }
    if (tid < 64) { m_s[tid] = -1e30f; l_s[tid] = 0.f; }

    float acc[4][8];
#pragma unroll
    for (int i = 0; i < 4; i++)
#pragma unroll
        for (int j = 0; j < 8; j++) acc[i][j] = 0.f;

    __syncthreads();

    const float sscale = 0.08838834764831845f;

    for (int kt = 0; kt <= qt; kt++) {
        const float* kg = Kg + (size_t)kt * 64 * HD;
        const float* vg = Vg + (size_t)kt * 64 * HD;
        for (int e = tid; e < 64 * 32; e += 256) {
            int r = e >> 5, c4 = (e & 31) << 2;
            float4 kv = *(const float4*)&kg[r * 128 + c4];
            Ks[r * 129 + c4 + 0] = kv.x;
            Ks[r * 129 + c4 + 1] = kv.y;
            Ks[r * 129 + c4 + 2] = kv.z;
            Ks[r * 129 + c4 + 3] = kv.w;
            *(float4*)&Vs[r * 128 + c4] = *(const float4*)&vg[r * 128 + c4];
        }
        __syncthreads();

        float s4[4][4];
#pragma unroll
        for (int i = 0; i < 4; i++)
#pragma unroll
            for (int j = 0; j < 4; j++) s4[i][j] = 0.f;

#pragma unroll 4
        for (int d = 0; d < 128; d++) {
            float qv[4], kv[4];
#pragma unroll
            for (int i = 0; i < 4; i++) qv[i] = Qs[(r0 + i) * 128 + d];
#pragma unroll
            for (int j = 0; j < 4; j++) kv[j] = Ks[(c0 + j) * 129 + d];
#pragma unroll
            for (int i = 0; i < 4; i++)
#pragma unroll
                for (int j = 0; j < 4; j++)
                    s4[i][j] = fmaf(qv[i], kv[j], s4[i][j]);
        }

        const bool diag = (kt == qt);
#pragma unroll
        for (int i = 0; i < 4; i++)
#pragma unroll
            for (int j = 0; j < 4; j++) {
                float val = s4[i][j] * sscale;
                if (diag && (c0 + j > r0 + i)) val = -1e30f;
                Ps[(r0 + i) * 65 + (c0 + j)] = val;
            }
        __syncthreads();

        if (tid < 64) {
            float* prow = Ps + tid * 65;
            float mold = m_s[tid];
            float mx = mold;
#pragma unroll 8
            for (int c = 0; c < 64; c++) mx = fmaxf(mx, prow[c]);
            float lsum = 0.f;
#pragma unroll 8
            for (int c = 0; c < 64; c++) {
                float p = __expf(prow[c] - mx);
                prow[c] = p;
                lsum += p;
            }
            float so = __expf(mold - mx);
            sc_s[tid] = so;
            m_s[tid] = mx;
            l_s[tid] = l_s[tid] * so + lsum;
        }
        __syncthreads();

#pragma unroll
        for (int i = 0; i < 4; i++) {
            float sc = sc_s[r0 + i];
#pragma unroll
            for (int j = 0; j < 8; j++) acc[i][j] *= sc;
        }
#pragma unroll 2
        for (int c = 0; c < 64; c++) {
            float p0 = Ps[(r0 + 0) * 65 + c];
            float p1 = Ps[(r0 + 1) * 65 + c];
            float p2 = Ps[(r0 + 2) * 65 + c];
            float p3 = Ps[(r0 + 3) * 65 + c];
            float4 va = *(const float4*)&Vs[c * 128 + cc];
            float4 vb = *(const float4*)&Vs[c * 128 + cc + 4];
            acc[0][0] = fmaf(p0, va.x, acc[0][0]);
            acc[0][1] = fmaf(p0, va.y, acc[0][1]);
            acc[0][2] = fmaf(p0, va.z, acc[0][2]);
            acc[0][3] = fmaf(p0, va.w, acc[0][3]);
            acc[0][4] = fmaf(p0, vb.x, acc[0][4]);
            acc[0][5] = fmaf(p0, vb.y, acc[0][5]);
            acc[0][6] = fmaf(p0, vb.z, acc[0][6]);
            acc[0][7] = fmaf(p0, vb.w, acc[0][7]);
            acc[1][0] = fmaf(p1, va.x, acc[1][0]);
            acc[1][1] = fmaf(p1, va.y, acc[1][1]);
            acc[1][2] = fmaf(p1, va.z, acc[1][2]);
            acc[1][3] = fmaf(p1, va.w, acc[1][3]);
            acc[1][4] = fmaf(p1, vb.x, acc[1][4]);
            acc[1][5] = fmaf(p1, vb.y, acc[1][5]);
            acc[1][6] = fmaf(p1, vb.z, acc[1][6]);
            acc[1][7] = fmaf(p1, vb.w, acc[1][7]);
            acc[2][0] = fmaf(p2, va.x, acc[2][0]);
            acc[2][1] = fmaf(p2, va.y, acc[2][1]);
            acc[2][2] = fmaf(p2, va.z, acc[2][2]);
            acc[2][3] = fmaf(p2, va.w, acc[2][3]);
            acc[2][4] = fmaf(p2, vb.x, acc[2][4]);
            acc[2][5] = fmaf(p2, vb.y, acc[2][5]);
            acc[2][6] = fmaf(p2, vb.z, acc[2][6]);
            acc[2][7] = fmaf(p2, vb.w, acc[2][7]);
            acc[3][0] = fmaf(p3, va.x, acc[3][0]);
            acc[3][1] = fmaf(p3, va.y, acc[3][1]);
            acc[3][2] = fmaf(p3, va.z, acc[3][2]);
            acc[3][3] = fmaf(p3, va.w, acc[3][3]);
            acc[3][4] = fmaf(p3, vb.x, acc[3][4]);
            acc[3][5] = fmaf(p3, vb.y, acc[3][5]);
            acc[3][6] = fmaf(p3, vb.z, acc[3][6]);
            acc[3][7] = fmaf(p3, vb.w, acc[3][7]);
        }
        __syncthreads();
    }

#pragma unroll
    for (int i = 0; i < 4; i++) {
        float inv = 1.f / l_s[r0 + i];
        int sg = qt * 64 + r0 + i;
        float* og = O + ((size_t)(b * Ss + sg) * Hh + u) * HD + cc;
        *(float4*)&og[0] = make_float4(acc[i][0] * inv, acc[i][1] * inv,
                                       acc[i][2] * inv, acc[i][3] * inv);
        *(float4*)&og[4] = make_float4(acc[i][4] * inv, acc[i][5] * inv,
                                       acc[i][6] * inv, acc[i][7] * inv);
    }
}

// =====================================================================
// launch
// =====================================================================
extern "C" void kernel_launch(void* const* d_in, const int* in_sizes, int n_in,
                              void* d_out, int out_size)
{
    const float *X = 0, *Wq = 0, *Wk = 0, *Wv = 0, *Wo = 0;
    int seen_big = 0, seen_mid = 0, seen_small = 0;
    for (int i = 0; i < n_in; i++) {
        long sz = in_sizes[i];
        if (sz == 8388608) {
            if (seen_big == 0) X = (const float*)d_in[i];
            seen_big++;
        } else if (sz == 4194304) {
            if (seen_mid == 0) Wq = (const float*)d_in[i];
            else               Wo = (const float*)d_in[i];
            seen_mid++;
        } else if (sz == 1048576) {
            if (seen_small == 0) Wk = (const float*)d_in[i];
            else                 Wv = (const float*)d_in[i];
            seen_small++;
        }
    }
    if (!X || !Wq || !Wk || !Wv || !Wo) {
        X  = (const float*)d_in[0];
        Wq = (const float*)d_in[2];
        Wk = (const float*)d_in[3];
        Wv = (const float*)d_in[4];
        Wo = (const float*)d_in[5];
    }
    float* out = (float*)d_out;

    float *Cq, *Ck, *Cv, *Qp, *Kp, *Vp, *attn;
    __nv_bfloat16 *Xh, *Xl, *Ath, *Atl, *Wqh, *Wql, *Wkh, *Wkl, *Wvh, *Wvl, *Woh, *Wol;
    cudaGetSymbolAddress((void**)&Cq,   g_Cq);
    cudaGetSymbolAddress((void**)&Ck,   g_Ck);
    cudaGetSymbolAddress((void**)&Cv,   g_Cv);
    cudaGetSymbolAddress((void**)&Qp,   g_Q);
    cudaGetSymbolAddress((void**)&Kp,   g_K);
    cudaGetSymbolAddress((void**)&Vp,   g_V);
    cudaGetSymbolAddress((void**)&attn, g_attn);
    cudaGetSymbolAddress((void**)&Xh,  g_Xh);   cudaGetSymbolAddress((void**)&Xl,  g_Xl);
    cudaGetSymbolAddress((void**)&Ath, g_Ath);  cudaGetSymbolAddress((void**)&Atl, g_Atl);
    cudaGetSymbolAddress((void**)&Wqh, g_Wqh);  cudaGetSymbolAddress((void**)&Wql, g_Wql);
    cudaGetSymbolAddress((void**)&Wkh, g_Wkh);  cudaGetSymbolAddress((void**)&Wkl, g_Wkl);
    cudaGetSymbolAddress((void**)&Wvh, g_Wvh);  cudaGetSymbolAddress((void**)&Wvl, g_Wvl);
    cudaGetSymbolAddress((void**)&Woh, g_Woh);  cudaGetSymbolAddress((void**)&Wol, g_Wol);

    cudaFuncSetAttribute(gemm_bf16x3, cudaFuncAttributeMaxDynamicSharedMemorySize, GEMM_SMEM);
    cudaFuncSetAttribute(attn_kernel, cudaFuncAttributeMaxDynamicSharedMemorySize, ATTN_SMEM_BYTES);

    // split / transpose operands
    split_kernel <<<(Mrows * Dd / 4 + 255) / 256, 256>>>(X, Xh, Xl, Mrows * Dd / 4);
    split_t_kernel<<<dim3(2048 / 32, 2048 / 32), dim3(32, 8)>>>(Wq, Wqh, Wql, 2048, 2048);
    split_t_kernel<<<dim3(512 / 32,  2048 / 32), dim3(32, 8)>>>(Wk, Wkh, Wkl, 2048, 512);
    split_t_kernel<<<dim3(512 / 32,  2048 / 32), dim3(32, 8)>>>(Wv, Wvh, Wvl, 2048, 512);
    split_t_kernel<<<dim3(2048 / 32, 2048 / 32), dim3(32, 8)>>>(Wo, Woh, Wol, 2048, 2048);

    // QKV projections (tensor cores)
    gemm_bf16x3<<<dim3(2048 / 128, Mrows / 128), 256, GEMM_SMEM>>>(Xh, Xl, Wqh, Wql, Cq, Mrows, 2048, 2048);
    gemm_bf16x3<<<dim3(512 / 128,  Mrows / 128), 256, GEMM_SMEM>>>(Xh, Xl, Wkh, Wkl, Ck, Mrows, 512, 2048);
    gemm_bf16x3<<<dim3(512 / 128,  Mrows / 128), 256, GEMM_SMEM>>>(Xh, Xl, Wvh, Wvl, Cv, Mrows, 512, 2048);

    // Fused RoPE + transpose
    rope_all_kernel<<<dim3(Ss, Bb), 256>>>(Cq, Ck, Cv, Qp, Kp, Vp);

    // Flash attention (fp32)
    attn_kernel<<<dim3(Ss / 64, Hh, Bb), 256, ATTN_SMEM_BYTES>>>(Qp, Kp, Vp, attn);

    // Output projection
    split_kernel<<<(Mrows * Dd / 4 + 255) / 256, 256>>>(attn, Ath, Atl, Mrows * Dd / 4);
    gemm_bf16x3<<<dim3(2048 / 128, Mrows / 128), 256, GEMM_SMEM>>>(Ath, Atl, Woh, Wol, out, Mrows, 2048, 2048);
}

// round 7
// speedup vs baseline: 10.4153x; 1.8780x over previous
#include <cuda_runtime.h>
#include <cuda_bf16.h>
#include <math.h>
#include <stdint.h>

// Problem constants
#define Bb   2
#define Ss   2048
#define Dd   2048
#define Hh   16
#define KVh  4
#define HD   128
#define Mrows (Bb*Ss)          // 4096

// ---------------- scratch (device globals; no allocation) ----------------
__device__ float g_Cq[Mrows * (Hh*HD)];     // 4096 x 2048
__device__ float g_Ck[Mrows * (KVh*HD)];    // 4096 x 512
__device__ float g_Cv[Mrows * (KVh*HD)];    // 4096 x 512

// bf16 hi/lo split operands
__device__ __nv_bfloat16 g_Xh[Mrows*Dd],  g_Xl[Mrows*Dd];        // X  [M][K]
__device__ __nv_bfloat16 g_Ath[Mrows*Dd], g_Atl[Mrows*Dd];       // attn [M][K]
__device__ __nv_bfloat16 g_Wqh[Dd*Dd],    g_Wql[Dd*Dd];          // Wq^T [N][K]
__device__ __nv_bfloat16 g_Wkh[512*Dd],   g_Wkl[512*Dd];         // Wk^T
__device__ __nv_bfloat16 g_Wvh[512*Dd],   g_Wvl[512*Dd];         // Wv^T
__device__ __nv_bfloat16 g_Woh[Dd*Dd],    g_Wol[Dd*Dd];          // Wo^T

// attention operands (bf16 hi/lo)
__device__ __nv_bfloat16 g_Qh[Bb*Hh*Ss*HD],  g_Ql[Bb*Hh*Ss*HD];    // (B,H,S,HD), pre-scaled
__device__ __nv_bfloat16 g_Kh[Bb*KVh*Ss*HD], g_Kl[Bb*KVh*Ss*HD];   // (B,KV,S,HD)
__device__ __nv_bfloat16 g_Vth[Bb*KVh*HD*Ss],g_Vtl[Bb*KVh*HD*Ss];  // (B,KV,HD,S) transposed

// =====================================================================
// helpers
// =====================================================================
#define CP_ASYNC16(daddr, gptr) \
    asm volatile("cp.async.cg.shared.global [%0], [%1], 16;\n" :: "r"(daddr), "l"(gptr))
#define CP_COMMIT()  asm volatile("cp.async.commit_group;\n" ::)
#define CP_WAIT(n)   asm volatile("cp.async.wait_group %0;\n" :: "n"(n))

#define MMA_BF16(d, a, b) \
    asm volatile("mma.sync.aligned.m16n8k16.row.col.f32.bf16.bf16.f32 " \
        "{%0,%1,%2,%3}, {%4,%5,%6,%7}, {%8,%9}, {%0,%1,%2,%3};\n" \
        : "+f"(d[0]), "+f"(d[1]), "+f"(d[2]), "+f"(d[3]) \
        : "r"(a[0]), "r"(a[1]), "r"(a[2]), "r"(a[3]), "r"(b[0]), "r"(b[1]))

// pack two fp32 -> bf16x2 hi reg + residual lo reg (function, not macro!)
__device__ __forceinline__ void pkhl(uint32_t& dsth, uint32_t& dstl, float a, float b)
{
    __nv_bfloat162 h = __floats2bfloat162_rn(a, b);
    dsth = *(uint32_t*)&h;
    __nv_bfloat162 l = __floats2bfloat162_rn(a - __bfloat162float(h.x),
                                             b - __bfloat162float(h.y));
    dstl = *(uint32_t*)&l;
}

// =====================================================================
// split: fp32 -> bf16 hi + bf16 lo, float4 per thread
// =====================================================================
__global__ __launch_bounds__(256)
void split_kernel(const float* __restrict__ in, __nv_bfloat16* __restrict__ hi,
                  __nv_bfloat16* __restrict__ lo, int n4)
{
    int i = blockIdx.x * 256 + threadIdx.x;
    if (i >= n4) return;
    float4 x = ((const float4*)in)[i];
    __nv_bfloat16 h0 = __float2bfloat16(x.x), h1 = __float2bfloat16(x.y);
    __nv_bfloat16 h2 = __float2bfloat16(x.z), h3 = __float2bfloat16(x.w);
    __nv_bfloat16 l0 = __float2bfloat16(x.x - __bfloat162float(h0));
    __nv_bfloat16 l1 = __float2bfloat16(x.y - __bfloat162float(h1));
    __nv_bfloat16 l2 = __float2bfloat16(x.z - __bfloat162float(h2));
    __nv_bfloat16 l3 = __float2bfloat16(x.w - __bfloat162float(h3));
    ((__nv_bfloat162*)hi)[i*2]   = __nv_bfloat162(h0, h1);
    ((__nv_bfloat162*)hi)[i*2+1] = __nv_bfloat162(h2, h3);
    ((__nv_bfloat162*)lo)[i*2]   = __nv_bfloat162(l0, l1);
    ((__nv_bfloat162*)lo)[i*2+1] = __nv_bfloat162(l2, l3);
}

// =====================================================================
// split + transpose: W [K][N] fp32 -> Th/Tl [N][K] bf16
// =====================================================================
__global__ __launch_bounds__(256)
void split_t_kernel(const float* __restrict__ W, __nv_bfloat16* __restrict__ Th,
                    __nv_bfloat16* __restrict__ Tl, int K, int N)
{
    __shared__ float t[32][33];
    const int nb = blockIdx.x * 32, kb = blockIdx.y * 32;
    const int tx = threadIdx.x, ty = threadIdx.y;   // 32 x 8
#pragma unroll
    for (int i = 0; i < 32; i += 8)
        t[ty + i][tx] = W[(size_t)(kb + ty + i) * N + nb + tx];
    __syncthreads();
#pragma unroll
    for (int i = 0; i < 32; i += 8) {
        float x = t[tx][ty + i];
        __nv_bfloat16 h = __float2bfloat16(x);
        size_t o = (size_t)(nb + ty + i) * K + kb + tx;
        Th[o] = h;
        Tl[o] = __float2bfloat16(x - __bfloat162float(h));
    }
}

// =====================================================================
// GEMM (bf16x3): C[M][N] fp32 = (Ah+Al)[M][K] @ (Bh+Bl)[N][K]^T
// =====================================================================
#define GPL 5120            // plane: 128 rows * 40 halves
#define GEMM_SMEM (2*2*2*GPL*2)   // 81920

__device__ __forceinline__ void gemm_fill(
    const __nv_bfloat16* Ah, const __nv_bfloat16* Al,
    const __nv_bfloat16* Bh, const __nv_bfloat16* Bl,
    int K, int m0, int n0, int k0, uint32_t sbase, int buf, int tid)
{
#pragma unroll
    for (int j = 0; j < 8; j++) {
        int e = tid + j * 256;
        int mat = e >> 10, part = (e >> 9) & 1, idx = e & 511;
        int row = idx >> 2, seg = idx & 3;
        const __nv_bfloat16* g;
        if (mat == 0) g = (part ? Al : Ah) + (size_t)(m0 + row) * K + k0 + seg * 8;
        else          g = (part ? Bl : Bh) + (size_t)(n0 + row) * K + k0 + seg * 8;
        uint32_t daddr = sbase +
            (uint32_t)((((mat * 2 + buf) * 2 + part) * GPL + row * 40 + seg * 8) * 2);
        CP_ASYNC16(daddr, g);
    }
}

__global__ __launch_bounds__(256)
void gemm_bf16x3(const __nv_bfloat16* __restrict__ Ah, const __nv_bfloat16* __restrict__ Al,
                 const __nv_bfloat16* __restrict__ Bh, const __nv_bfloat16* __restrict__ Bl,
                 float* __restrict__ C, int M, int N, int K)
{
    extern __shared__ __nv_bfloat16 smg[];
    const int tid = threadIdx.x;
    const int m0 = blockIdx.y * 128, n0 = blockIdx.x * 128;
    const int warp = tid >> 5, lane = tid & 31;
    const int g = lane >> 2, ctg = lane & 3;
    const int wm = (warp >> 2) * 64, wn = (warp & 3) * 32;
    const uint32_t sbase = (uint32_t)__cvta_generic_to_shared(smg);

    float acc[4][4][4];
#pragma unroll
    for (int a = 0; a < 4; a++)
#pragma unroll
        for (int b = 0; b < 4; b++)
#pragma unroll
            for (int c = 0; c < 4; c++) acc[a][b][c] = 0.f;

    const int nc = K / 32;
    gemm_fill(Ah, Al, Bh, Bl, K, m0, n0, 0, sbase, 0, tid);
    CP_COMMIT();

    for (int c = 0; c < nc; c++) {
        if (c + 1 < nc) {
            gemm_fill(Ah, Al, Bh, Bl, K, m0, n0, (c + 1) * 32, sbase, (c + 1) & 1, tid);
            CP_COMMIT();
            CP_WAIT(1);
        } else {
            CP_WAIT(0);
        }
        __syncthreads();

        const int buf = c & 1;
        const __nv_bfloat16* Ahs = smg + ((0 * 2 + buf) * 2 + 0) * GPL;
        const __nv_bfloat16* Als = smg + ((0 * 2 + buf) * 2 + 1) * GPL;
        const __nv_bfloat16* Bhs = smg + ((1 * 2 + buf) * 2 + 0) * GPL;
        const __nv_bfloat16* Bls = smg + ((1 * 2 + buf) * 2 + 1) * GPL;

#pragma unroll
        for (int kk = 0; kk < 32; kk += 16) {
            uint32_t ah[4][4], al[4][4], bh[4][2], bl[4][2];
#pragma unroll
            for (int mf = 0; mf < 4; mf++) {
                int o = (wm + mf * 16 + g) * 40 + kk + 2 * ctg;
                ah[mf][0] = *(const uint32_t*)&Ahs[o];
                ah[mf][1] = *(const uint32_t*)&Ahs[o + 8 * 40];
                ah[mf][2] = *(const uint32_t*)&Ahs[o + 8];
                ah[mf][3] = *(const uint32_t*)&Ahs[o + 8 * 40 + 8];
                al[mf][0] = *(const uint32_t*)&Als[o];
                al[mf][1] = *(const uint32_t*)&Als[o + 8 * 40];
                al[mf][2] = *(const uint32_t*)&Als[o + 8];
                al[mf][3] = *(const uint32_t*)&Als[o + 8 * 40 + 8];
            }
#pragma unroll
            for (int nf = 0; nf < 4; nf++) {
                int o = (wn + nf * 8 + g) * 40 + kk + 2 * ctg;
                bh[nf][0] = *(const uint32_t*)&Bhs[o];
                bh[nf][1] = *(const uint32_t*)&Bhs[o + 8];
                bl[nf][0] = *(const uint32_t*)&Bls[o];
                bl[nf][1] = *(const uint32_t*)&Bls[o + 8];
            }
#pragma unroll
            for (int mf = 0; mf < 4; mf++)
#pragma unroll
                for (int nf = 0; nf < 4; nf++) MMA_BF16(acc[mf][nf], ah[mf], bh[nf]);
#pragma unroll
            for (int mf = 0; mf < 4; mf++)
#pragma unroll
                for (int nf = 0; nf < 4; nf++) MMA_BF16(acc[mf][nf], ah[mf], bl[nf]);
#pragma unroll
            for (int mf = 0; mf < 4; mf++)
#pragma unroll
                for (int nf = 0; nf < 4; nf++) MMA_BF16(acc[mf][nf], al[mf], bh[nf]);
        }
        __syncthreads();
    }

#pragma unroll
    for (int mf = 0; mf < 4; mf++)
#pragma unroll
        for (int nf = 0; nf < 4; nf++) {
            int r  = m0 + wm + mf * 16 + g;
            int cl = n0 + wn + nf * 8 + 2 * ctg;
            *(float2*)&C[(size_t)r * N + cl]       = make_float2(acc[mf][nf][0], acc[mf][nf][1]);
            *(float2*)&C[(size_t)(r + 8) * N + cl] = make_float2(acc[mf][nf][2], acc[mf][nf][3]);
        }
}

// =====================================================================
// RoPE: Cq/Ck fp32 -> Qh/Ql (scaled by 1/sqrt(HD)) and Kh/Kl bf16,
// layouts (B,H,S,HD) / (B,KV,S,HD). One block per (s, b).
// =====================================================================
__global__ __launch_bounds__(256)
void rope_qk_kernel(const float* __restrict__ Cq, const float* __restrict__ Ck,
                    __nv_bfloat16* __restrict__ Qh, __nv_bfloat16* __restrict__ Ql,
                    __nv_bfloat16* __restrict__ Kh, __nv_bfloat16* __restrict__ Kl)
{
    __shared__ float cs[64], sn[64];
    const int s = blockIdx.x, b = blockIdx.y;
    const int tid = threadIdx.x;
    const float sscale = 0.08838834764831845f;   // 1/sqrt(128)

    if (tid < 64) {
        double f = pow(10000.0, -(double)tid / 64.0);
        double a = (double)s * f;
        cs[tid] = (float)cos(a);
        sn[tid] = (float)sin(a);
    }
    __syncthreads();

    const float* cq = Cq + (size_t)(b * Ss + s) * (Hh * HD);
    for (int p = tid; p < Hh * 64; p += 256) {
        int u = p >> 6, i = p & 63;
        float x1 = cq[u * HD + i], x2 = cq[u * HD + i + 64];
        float c = cs[i], sv = sn[i];
        float y1 = (x1 * c - x2 * sv) * sscale;
        float y2 = (x2 * c + x1 * sv) * sscale;
        size_t dst = ((size_t)(b * Hh + u) * Ss + s) * HD;
        __nv_bfloat16 h1 = __float2bfloat16(y1), h2 = __float2bfloat16(y2);
        Qh[dst + i]      = h1;
        Qh[dst + i + 64] = h2;
        Ql[dst + i]      = __float2bfloat16(y1 - __bfloat162float(h1));
        Ql[dst + i + 64] = __float2bfloat16(y2 - __bfloat162float(h2));
    }

    const float* ck = Ck + (size_t)(b * Ss + s) * (KVh * HD);
    for (int p = tid; p < KVh * 64; p += 256) {
        int u = p >> 6, i = p & 63;
        float x1 = ck[u * HD + i], x2 = ck[u * HD + i + 64];
        float c = cs[i], sv = sn[i];
        float y1 = x1 * c - x2 * sv;
        float y2 = x2 * c + x1 * sv;
        size_t dst = ((size_t)(b * KVh + u) * Ss + s) * HD;
        __nv_bfloat16 h1 = __float2bfloat16(y1), h2 = __float2bfloat16(y2);
        Kh[dst + i]      = h1;
        Kh[dst + i + 64] = h2;
        Kl[dst + i]      = __float2bfloat16(y1 - __bfloat162float(h1));
        Kl[dst + i + 64] = __float2bfloat16(y2 - __bfloat162float(h2));
    }
}

// =====================================================================
// V transpose + split: Cv [b*S+s][kv*HD+d] fp32 -> Vt [b,kv,d,s] bf16 hi/lo
// =====================================================================
__global__ __launch_bounds__(256)
void transpose_v_kernel(const float* __restrict__ Cv,
                        __nv_bfloat16* __restrict__ Vth, __nv_bfloat16* __restrict__ Vtl)
{
    __shared__ float t[32][33];
    const int s0 = blockIdx.x * 32, d0 = blockIdx.y * 32;
    const int bkv = blockIdx.z;
    const int b = bkv >> 2, kv = bkv & 3;
    const int tx = threadIdx.x, ty = threadIdx.y;   // 32 x 8

#pragma unroll
    for (int i = 0; i < 32; i += 8)
        t[ty + i][tx] = Cv[(size_t)(b * Ss + s0 + ty + i) * (KVh * HD) + kv * HD + d0 + tx];
    __syncthreads();
#pragma unroll
    for (int i = 0; i < 32; i += 8) {
        float x = t[tx][ty + i];
        __nv_bfloat16 h = __float2bfloat16(x);
        size_t o = ((size_t)(b * KVh + kv) * HD + d0 + ty + i) * Ss + s0 + tx;
        Vth[o] = h;
        Vtl[o] = __float2bfloat16(x - __bfloat162float(h));
    }
}

// =====================================================================
// Flash attention on tensor cores (bf16x3, causal, GQA).
// BQ=128, BK=64. 8 warps; warp = 16 q-rows. Q in registers.
// K smem [64][136] hi/lo, Vt smem [128][72] hi/lo, double buffered.
// Output: bf16 hi/lo directly into Ath/Atl (B,S,H*HD).
// =====================================================================
#define KPL  8704            // 64*136 halves
#define VPL  9216            // 128*72 halves
#define ABUF (2*KPL + 2*VPL) // 35840 halves per buffer
#define ATTN_SMEM (2*ABUF*2) // 143360 bytes

__device__ __forceinline__ void attn_fill(
    const __nv_bfloat16* Khg, const __nv_bfloat16* Klg,
    const __nv_bfloat16* Vthg, const __nv_bfloat16* Vtlg,
    int kt, uint32_t sbase, int buf, int tid)
{
    uint32_t b0 = sbase + (uint32_t)(buf * ABUF * 2);
#pragma unroll
    for (int j = 0; j < 16; j++) {
        int e = tid + j * 256;
        if (e < 2048) {                     // K hi/lo: 64 rows x 16 chunks
            int part = e >> 10, idx = e & 1023;
            int row = idx >> 4, ch = idx & 15;
            const __nv_bfloat16* g = (part ? Klg : Khg) +
                (size_t)(kt * 64 + row) * HD + ch * 8;
            CP_ASYNC16(b0 + (uint32_t)((part * KPL + row * 136 + ch * 8) * 2), g);
        } else {                            // Vt hi/lo: 128 rows x 8 chunks
            int e2 = e - 2048;
            int part = e2 >> 10, idx = e2 & 1023;
            int row = idx >> 3, ch = idx & 7;
            const __nv_bfloat16* g = (part ? Vtlg : Vthg) +
                (size_t)row * Ss + kt * 64 + ch * 8;
            CP_ASYNC16(b0 + (uint32_t)((2 * KPL + part * VPL + row * 72 + ch * 8) * 2), g);
        }
    }
}

__global__ __launch_bounds__(256, 1)
void attn_mma_kernel(const __nv_bfloat16* __restrict__ Qh, const __nv_bfloat16* __restrict__ Ql,
                     const __nv_bfloat16* __restrict__ Khg, const __nv_bfloat16* __restrict__ Klg,
                     const __nv_bfloat16* __restrict__ Vthg, const __nv_bfloat16* __restrict__ Vtlg,
                     __nv_bfloat16* __restrict__ Ath, __nv_bfloat16* __restrict__ Atl)
{
    extern __shared__ __nv_bfloat16 sma[];
    const int qt = (int)gridDim.x - 1 - (int)blockIdx.x;   // reversed for balance
    const int u = blockIdx.y, b = blockIdx.z;
    const int tid = threadIdx.x;
    const int wid = tid >> 5, lane = tid & 31;
    const int g = lane >> 2, ctg = lane & 3;
    const uint32_t sbase = (uint32_t)__cvta_generic_to_shared(sma);

    const __nv_bfloat16* Kg  = Khg  + (size_t)(b * KVh + (u >> 2)) * Ss * HD;
    const __nv_bfloat16* Klg2= Klg  + (size_t)(b * KVh + (u >> 2)) * Ss * HD;
    const __nv_bfloat16* Vhg = Vthg + (size_t)(b * KVh + (u >> 2)) * HD * Ss;
    const __nv_bfloat16* Vlg = Vtlg + (size_t)(b * KVh + (u >> 2)) * HD * Ss;

    // load Q fragments (16 rows per warp) into registers
    uint32_t qh[8][4], ql[8][4];
    {
        const __nv_bfloat16* Qbase_h = Qh + ((size_t)(b * Hh + u) * Ss + qt * 128 + wid * 16) * HD;
        const __nv_bfloat16* Qbase_l = Ql + ((size_t)(b * Hh + u) * Ss + qt * 128 + wid * 16) * HD;
#pragma unroll
        for (int ks = 0; ks < 8; ks++) {
            int klo = ks * 16 + 2 * ctg;
            qh[ks][0] = *(const uint32_t*)&Qbase_h[(size_t)g * HD + klo];
            qh[ks][1] = *(const uint32_t*)&Qbase_h[(size_t)(g + 8) * HD + klo];
            qh[ks][2] = *(const uint32_t*)&Qbase_h[(size_t)g * HD + klo + 8];
            qh[ks][3] = *(const uint32_t*)&Qbase_h[(size_t)(g + 8) * HD + klo + 8];
            ql[ks][0] = *(const uint32_t*)&Qbase_l[(size_t)g * HD + klo];
            ql[ks][1] = *(const uint32_t*)&Qbase_l[(size_t)(g + 8) * HD + klo];
            ql[ks][2] = *(const uint32_t*)&Qbase_l[(size_t)g * HD + klo + 8];
            ql[ks][3] = *(const uint32_t*)&Qbase_l[(size_t)(g + 8) * HD + klo + 8];
        }
    }

    float o[16][4];
#pragma unroll
    for (int nf = 0; nf < 16; nf++)
#pragma unroll
        for (int c = 0; c < 4; c++) o[nf][c] = 0.f;
    float m0 = -1e30f, m1 = -1e30f, l0 = 0.f, l1 = 0.f;

    const int row0 = qt * 128 + wid * 16 + g;
    const int row1 = row0 + 8;
    const int nkt = 2 * qt + 2;

    attn_fill(Kg, Klg2, Vhg, Vlg, 0, sbase, 0, tid);
    CP_COMMIT();

    for (int kt = 0; kt < nkt; kt++) {
        if (kt + 1 < nkt) {
            attn_fill(Kg, Klg2, Vhg, Vlg, kt + 1, sbase, (kt + 1) & 1, tid);
            CP_COMMIT();
            CP_WAIT(1);
        } else {
            CP_WAIT(0);
        }
        __syncthreads();

        const int buf = kt & 1;
        const __nv_bfloat16* Khs = sma + buf * ABUF;
        const __nv_bfloat16* Kls = Khs + KPL;
        const __nv_bfloat16* Vhs = Khs + 2 * KPL;
        const __nv_bfloat16* Vls = Vhs + VPL;

        // ---- scores S = Q K^T (16 x 64) ----
        float sf[8][4];
#pragma unroll
        for (int nf = 0; nf < 8; nf++)
#pragma unroll
            for (int c = 0; c < 4; c++) sf[nf][c] = 0.f;

#pragma unroll
        for (int ks = 0; ks < 8; ks++) {
#pragma unroll
            for (int nf = 0; nf < 8; nf++) {
                int so = (nf * 8 + g) * 136 + ks * 16 + 2 * ctg;
                uint32_t bh[2], bl[2];
                bh[0] = *(const uint32_t*)&Khs[so];
                bh[1] = *(const uint32_t*)&Khs[so + 8];
                bl[0] = *(const uint32_t*)&Kls[so];
                bl[1] = *(const uint32_t*)&Kls[so + 8];
                MMA_BF16(sf[nf], qh[ks], bh);
                MMA_BF16(sf[nf], ql[ks], bh);
                MMA_BF16(sf[nf], qh[ks], bl);
            }
        }

        // ---- causal mask (only last two k-tiles can clip) ----
        if (kt >= 2 * qt) {
            const int colb = kt * 64 + 2 * ctg;
#pragma unroll
            for (int nf = 0; nf < 8; nf++) {
                int c0 = colb + nf * 8;
                if (c0     > row0) sf[nf][0] = -1e30f;
                if (c0 + 1 > row0) sf[nf][1] = -1e30f;
                if (c0     > row1) sf[nf][2] = -1e30f;
                if (c0 + 1 > row1) sf[nf][3] = -1e30f;
            }
        }

        // ---- online softmax ----
        float mx0 = m0, mx1 = m1;
#pragma unroll
        for (int nf = 0; nf < 8; nf++) {
            mx0 = fmaxf(mx0, fmaxf(sf[nf][0], sf[nf][1]));
            mx1 = fmaxf(mx1, fmaxf(sf[nf][2], sf[nf][3]));
        }
        mx0 = fmaxf(mx0, __shfl_xor_sync(0xffffffffu, mx0, 1));
        mx0 = fmaxf(mx0, __shfl_xor_sync(0xffffffffu, mx0, 2));
        mx1 = fmaxf(mx1, __shfl_xor_sync(0xffffffffu, mx1, 1));
        mx1 = fmaxf(mx1, __shfl_xor_sync(0xffffffffu, mx1, 2));

        float a0 = __expf(m0 - mx0), a1 = __expf(m1 - mx1);
        m0 = mx0; m1 = mx1;

        float s0 = 0.f, s1 = 0.f;
#pragma unroll
        for (int nf = 0; nf < 8; nf++) {
            sf[nf][0] = __expf(sf[nf][0] - mx0);
            sf[nf][1] = __expf(sf[nf][1] - mx0);
            sf[nf][2] = __expf(sf[nf][2] - mx1);
            sf[nf][3] = __expf(sf[nf][3] - mx1);
            s0 += sf[nf][0] + sf[nf][1];
            s1 += sf[nf][2] + sf[nf][3];
        }
        s0 += __shfl_xor_sync(0xffffffffu, s0, 1);
        s0 += __shfl_xor_sync(0xffffffffu, s0, 2);
        s1 += __shfl_xor_sync(0xffffffffu, s1, 1);
        s1 += __shfl_xor_sync(0xffffffffu, s1, 2);
        l0 = l0 * a0 + s0;
        l1 = l1 * a1 + s1;

#pragma unroll
        for (int nf = 0; nf < 16; nf++) {
            o[nf][0] *= a0; o[nf][1] *= a0;
            o[nf][2] *= a1; o[nf][3] *= a1;
        }

        // ---- P fp32 -> bf16 hi/lo A-fragments (register-only) ----
        uint32_t ph[4][4], pl[4][4];
#pragma unroll
        for (int ks = 0; ks < 4; ks++) {
            pkhl(ph[ks][0], pl[ks][0], sf[2*ks][0],   sf[2*ks][1]);
            pkhl(ph[ks][1], pl[ks][1], sf[2*ks][2],   sf[2*ks][3]);
            pkhl(ph[ks][2], pl[ks][2], sf[2*ks+1][0], sf[2*ks+1][1]);
            pkhl(ph[ks][3], pl[ks][3], sf[2*ks+1][2], sf[2*ks+1][3]);
        }

        // ---- O += P V (16 x 128) ----
#pragma unroll
        for (int ks = 0; ks < 4; ks++) {
#pragma unroll
            for (int nf = 0; nf < 16; nf++) {
                int vo = (nf * 8 + g) * 72 + ks * 16 + 2 * ctg;
                uint32_t vh[2], vl[2];
                vh[0] = *(const uint32_t*)&Vhs[vo];
                vh[1] = *(const uint32_t*)&Vhs[vo + 8];
                vl[0] = *(const uint32_t*)&Vls[vo];
                vl[1] = *(const uint32_t*)&Vls[vo + 8];
                MMA_BF16(o[nf], ph[ks], vh);
                MMA_BF16(o[nf], pl[ks], vh);
                MMA_BF16(o[nf], ph[ks], vl);
            }
        }
        __syncthreads();
    }

    // ---- epilogue: O/l -> bf16 hi/lo into Ath/Atl (B,S,H*HD) ----
    const float inv0 = 1.f / l0, inv1 = 1.f / l1;
    const size_t rg0 = (size_t)(b * Ss + qt * 128 + wid * 16 + g) * 2048;
    const size_t rg1 = rg0 + 8 * 2048;
#pragma unroll
    for (int nf = 0; nf < 16; nf++) {
        int col = u * 128 + nf * 8 + 2 * ctg;
        uint32_t h, l;
        pkhl(h, l, o[nf][0] * inv0, o[nf][1] * inv0);
        *(uint32_t*)&Ath[rg0 + col] = h;
        *(uint32_t*)&Atl[rg0 + col] = l;
        pkhl(h, l, o[nf][2] * inv1, o[nf][3] * inv1);
        *(uint32_t*)&Ath[rg1 + col] = h;
        *(uint32_t*)&Atl[rg1 + col] = l;
    }
}

// =====================================================================
// launch
// =====================================================================
extern "C" void kernel_launch(void* const* d_in, const int* in_sizes, int n_in,
                              void* d_out, int out_size)
{
    const float *X = 0, *Wq = 0, *Wk = 0, *Wv = 0, *Wo = 0;
    int seen_big = 0, seen_mid = 0, seen_small = 0;
    for (int i = 0; i < n_in; i++) {
        long sz = in_sizes[i];
        if (sz == 8388608) {
            if (seen_big == 0) X = (const float*)d_in[i];
            seen_big++;
        } else if (sz == 4194304) {
            if (seen_mid == 0) Wq = (const float*)d_in[i];
            else               Wo = (const float*)d_in[i];
            seen_mid++;
        } else if (sz == 1048576) {
            if (seen_small == 0) Wk = (const float*)d_in[i];
            else                 Wv = (const float*)d_in[i];
            seen_small++;
        }
    }
    if (!X || !Wq || !Wk || !Wv || !Wo) {
        X  = (const float*)d_in[0];
        Wq = (const float*)d_in[2];
        Wk = (const float*)d_in[3];
        Wv = (const float*)d_in[4];
        Wo = (const float*)d_in[5];
    }
    float* out = (float*)d_out;

    float *Cq, *Ck, *Cv;
    __nv_bfloat16 *Xh, *Xl, *Ath, *Atl, *Wqh, *Wql, *Wkh, *Wkl, *Wvh, *Wvl, *Woh, *Wol;
    __nv_bfloat16 *Qh, *Ql, *Kh, *Kl, *Vth, *Vtl;
    cudaGetSymbolAddress((void**)&Cq,   g_Cq);
    cudaGetSymbolAddress((void**)&Ck,   g_Ck);
    cudaGetSymbolAddress((void**)&Cv,   g_Cv);
    cudaGetSymbolAddress((void**)&Xh,  g_Xh);   cudaGetSymbolAddress((void**)&Xl,  g_Xl);
    cudaGetSymbolAddress((void**)&Ath, g_Ath);  cudaGetSymbolAddress((void**)&Atl, g_Atl);
    cudaGetSymbolAddress((void**)&Wqh, g_Wqh);  cudaGetSymbolAddress((void**)&Wql, g_Wql);
    cudaGetSymbolAddress((void**)&Wkh, g_Wkh);  cudaGetSymbolAddress((void**)&Wkl, g_Wkl);
    cudaGetSymbolAddress((void**)&Wvh, g_Wvh);  cudaGetSymbolAddress((void**)&Wvl, g_Wvl);
    cudaGetSymbolAddress((void**)&Woh, g_Woh);  cudaGetSymbolAddress((void**)&Wol, g_Wol);
    cudaGetSymbolAddress((void**)&Qh,  g_Qh);   cudaGetSymbolAddress((void**)&Ql,  g_Ql);
    cudaGetSymbolAddress((void**)&Kh,  g_Kh);   cudaGetSymbolAddress((void**)&Kl,  g_Kl);
    cudaGetSymbolAddress((void**)&Vth, g_Vth);  cudaGetSymbolAddress((void**)&Vtl, g_Vtl);

    cudaFuncSetAttribute(gemm_bf16x3,    cudaFuncAttributeMaxDynamicSharedMemorySize, GEMM_SMEM);
    cudaFuncSetAttribute(attn_mma_kernel,cudaFuncAttributeMaxDynamicSharedMemorySize, ATTN_SMEM);

    // operand prep
    split_kernel <<<(Mrows * Dd / 4 + 255) / 256, 256>>>(X, Xh, Xl, Mrows * Dd / 4);
    split_t_kernel<<<dim3(2048 / 32, 2048 / 32), dim3(32, 8)>>>(Wq, Wqh, Wql, 2048, 2048);
    split_t_kernel<<<dim3(512 / 32,  2048 / 32), dim3(32, 8)>>>(Wk, Wkh, Wkl, 2048, 512);
    split_t_kernel<<<dim3(512 / 32,  2048 / 32), dim3(32, 8)>>>(Wv, Wvh, Wvl, 2048, 512);
    split_t_kernel<<<dim3(2048 / 32, 2048 / 32), dim3(32, 8)>>>(Wo, Woh, Wol, 2048, 2048);

    // QKV projections (tensor cores)
    gemm_bf16x3<<<dim3(2048 / 128, Mrows / 128), 256, GEMM_SMEM>>>(Xh, Xl, Wqh, Wql, Cq, Mrows, 2048, 2048);
    gemm_bf16x3<<<dim3(512 / 128,  Mrows / 128), 256, GEMM_SMEM>>>(Xh, Xl, Wkh, Wkl, Ck, Mrows, 512, 2048);
    gemm_bf16x3<<<dim3(512 / 128,  Mrows / 128), 256, GEMM_SMEM>>>(Xh, Xl, Wvh, Wvl, Cv, Mrows, 512, 2048);

    // RoPE + layout + splits for attention
    rope_qk_kernel<<<dim3(Ss, Bb), 256>>>(Cq, Ck, Qh, Ql, Kh, Kl);
    transpose_v_kernel<<<dim3(Ss / 32, HD / 32, Bb * KVh), dim3(32, 8)>>>(Cv, Vth, Vtl);

    // Flash attention on tensor cores
    attn_mma_kernel<<<dim3(Ss / 128, Hh, Bb), 256, ATTN_SMEM>>>(Qh, Ql, Kh, Kl, Vth, Vtl, Ath, Atl);

    // Output projection
    gemm_bf16x3<<<dim3(2048 / 128, Mrows / 128), 256, GEMM_SMEM>>>(Ath, Atl, Woh, Wol, out, Mrows, 2048, 2048);
}

// round 9
// speedup vs baseline: 10.5390x; 1.0119x over previous
#include <cuda_runtime.h>
#include <cuda_bf16.h>
#include <math.h>
#include <stdint.h>

// Problem constants
#define Bb   2
#define Ss   2048
#define Dd   2048
#define Hh   16
#define KVh  4
#define HD   128
#define Mrows (Bb*Ss)          // 4096

// ---------------- scratch (device globals; no allocation) ----------------
__device__ float g_Cq[Mrows * (Hh*HD)];     // 4096 x 2048
__device__ float g_Ck[Mrows * (KVh*HD)];    // 4096 x 512
__device__ float g_Cv[Mrows * (KVh*HD)];    // 4096 x 512

// bf16 hi/lo split operands
__device__ __nv_bfloat16 g_Xh[Mrows*Dd],  g_Xl[Mrows*Dd];        // X  [M][K]
__device__ __nv_bfloat16 g_Ath[Mrows*Dd], g_Atl[Mrows*Dd];       // attn [M][K]
__device__ __nv_bfloat16 g_Wqh[Dd*Dd],    g_Wql[Dd*Dd];          // Wq^T [N][K]
__device__ __nv_bfloat16 g_Wkh[512*Dd],   g_Wkl[512*Dd];         // Wk^T
__device__ __nv_bfloat16 g_Wvh[512*Dd],   g_Wvl[512*Dd];         // Wv^T
__device__ __nv_bfloat16 g_Woh[Dd*Dd],    g_Wol[Dd*Dd];          // Wo^T

// attention operands (bf16 hi/lo)
__device__ __nv_bfloat16 g_Qh[Bb*Hh*Ss*HD],  g_Ql[Bb*Hh*Ss*HD];    // (B,H,S,HD), pre-scaled
__device__ __nv_bfloat16 g_Kh[Bb*KVh*Ss*HD], g_Kl[Bb*KVh*Ss*HD];   // (B,KV,S,HD)
__device__ __nv_bfloat16 g_Vth[Bb*KVh*HD*Ss],g_Vtl[Bb*KVh*HD*Ss];  // (B,KV,HD,S) transposed

// =====================================================================
// helpers
// =====================================================================
#define CP_ASYNC16(daddr, gptr) \
    asm volatile("cp.async.cg.shared.global [%0], [%1], 16;\n" :: "r"(daddr), "l"(gptr))
#define CP_COMMIT()  asm volatile("cp.async.commit_group;\n" ::)
#define CP_WAIT(n)   asm volatile("cp.async.wait_group %0;\n" :: "n"(n))

#define MMA_BF16(d, a, b) \
    asm volatile("mma.sync.aligned.m16n8k16.row.col.f32.bf16.bf16.f32 " \
        "{%0,%1,%2,%3}, {%4,%5,%6,%7}, {%8,%9}, {%0,%1,%2,%3};\n" \
        : "+f"(d[0]), "+f"(d[1]), "+f"(d[2]), "+f"(d[3]) \
        : "r"(a[0]), "r"(a[1]), "r"(a[2]), "r"(a[3]), "r"(b[0]), "r"(b[1]))

#define LDSM_X4(R0, R1, R2, R3, addr) \
    asm volatile("ldmatrix.sync.aligned.m8n8.x4.shared.b16 {%0,%1,%2,%3}, [%4];" \
        : "=r"(R0), "=r"(R1), "=r"(R2), "=r"(R3) : "r"(addr))

// pack two fp32 -> bf16x2 hi reg + residual lo reg
__device__ __forceinline__ void pkhl(uint32_t& dsth, uint32_t& dstl, float a, float b)
{
    __nv_bfloat162 h = __floats2bfloat162_rn(a, b);
    dsth = *(uint32_t*)&h;
    __nv_bfloat162 l = __floats2bfloat162_rn(a - __bfloat162float(h.x),
                                             b - __bfloat162float(h.y));
    dstl = *(uint32_t*)&l;
}

// =====================================================================
// split: fp32 -> bf16 hi + bf16 lo, float4 per thread
// =====================================================================
__global__ __launch_bounds__(256)
void split_kernel(const float* __restrict__ in, __nv_bfloat16* __restrict__ hi,
                  __nv_bfloat16* __restrict__ lo, int n4)
{
    int i = blockIdx.x * 256 + threadIdx.x;
    if (i >= n4) return;
    float4 x = ((const float4*)in)[i];
    __nv_bfloat16 h0 = __float2bfloat16(x.x), h1 = __float2bfloat16(x.y);
    __nv_bfloat16 h2 = __float2bfloat16(x.z), h3 = __float2bfloat16(x.w);
    __nv_bfloat16 l0 = __float2bfloat16(x.x - __bfloat162float(h0));
    __nv_bfloat16 l1 = __float2bfloat16(x.y - __bfloat162float(h1));
    __nv_bfloat16 l2 = __float2bfloat16(x.z - __bfloat162float(h2));
    __nv_bfloat16 l3 = __float2bfloat16(x.w - __bfloat162float(h3));
    ((__nv_bfloat162*)hi)[i*2]   = __nv_bfloat162(h0, h1);
    ((__nv_bfloat162*)hi)[i*2+1] = __nv_bfloat162(h2, h3);
    ((__nv_bfloat162*)lo)[i*2]   = __nv_bfloat162(l0, l1);
    ((__nv_bfloat162*)lo)[i*2+1] = __nv_bfloat162(l2, l3);
}

// =====================================================================
// split + transpose: W [K][N] fp32 -> Th/Tl [N][K] bf16
// =====================================================================
__global__ __launch_bounds__(256)
void split_t_kernel(const float* __restrict__ W, __nv_bfloat16* __restrict__ Th,
                    __nv_bfloat16* __restrict__ Tl, int K, int N)
{
    __shared__ float t[32][33];
    const int nb = blockIdx.x * 32, kb = blockIdx.y * 32;
    const int tx = threadIdx.x, ty = threadIdx.y;   // 32 x 8
#pragma unroll
    for (int i = 0; i < 32; i += 8)
        t[ty + i][tx] = W[(size_t)(kb + ty + i) * N + nb + tx];
    __syncthreads();
#pragma unroll
    for (int i = 0; i < 32; i += 8) {
        float x = t[tx][ty + i];
        __nv_bfloat16 h = __float2bfloat16(x);
        size_t o = (size_t)(nb + ty + i) * K + kb + tx;
        Th[o] = h;
        Tl[o] = __float2bfloat16(x - __bfloat162float(h));
    }
}

// =====================================================================
// GEMM v2 (bf16x3, mma.sync + ldmatrix): C = (Ah+Al) @ (Bh+Bl)^T
// CTA tile 128 x (32*NF), 8 warps (2m x 4n), warp tile 64 x (8*NF).
// K-chunk 32, stride-40 smem rows (LDSM conflict-free), double buffer.
// NF=8 -> CTA 128x256 (Q/O), NF=4 -> CTA 128x128 (K/V).
// =====================================================================
#define GPLA 5120                        // A plane: 128 rows * 40 halves

template<int NF>
__device__ __forceinline__ void g2_fill(
    const __nv_bfloat16* Ah, const __nv_bfloat16* Al,
    const __nv_bfloat16* Bh, const __nv_bfloat16* Bl,
    int K, int m0, int n0, int k0, uint32_t sbase, int buf, int tid)
{
    const int GPLB = 32 * NF * 40;
    const int BUFH = 2 * GPLA + 2 * GPLB;
    uint32_t base = sbase + (uint32_t)(buf * BUFH * 2);
#pragma unroll
    for (int j = 0; j < 4 + NF; j++) {
        int e = tid + j * 256;
        const __nv_bfloat16* gp;
        uint32_t soff;
        if (e < 1024) {                       // A hi/lo: 128 rows x 4 segs
            int part = e >> 9, idx = e & 511;
            int row = idx >> 2, seg = idx & 3;
            gp = (part ? Al : Ah) + (size_t)(m0 + row) * K + k0 + seg * 8;
            soff = (uint32_t)(part * GPLA + row * 40 + seg * 8);
        } else {                              // B hi/lo: 32*NF rows x 4 segs
            int e2 = e - 1024;
            int part = e2 / (128 * NF), idx = e2 % (128 * NF);
            int row = idx >> 2, seg = idx & 3;
            gp = (part ? Bl : Bh) + (size_t)(n0 + row) * K + k0 + seg * 8;
            soff = (uint32_t)(2 * GPLA + part * GPLB + row * 40 + seg * 8);
        }
        CP_ASYNC16(base + soff * 2, gp);
    }
}

template<int NF>
__global__ __launch_bounds__(256)
void gemm2(const __nv_bfloat16* __restrict__ Ah, const __nv_bfloat16* __restrict__ Al,
           const __nv_bfloat16* __restrict__ Bh, const __nv_bfloat16* __restrict__ Bl,
           float* __restrict__ C, int M, int N, int K)
{
    extern __shared__ __nv_bfloat16 smg[];
    const int GPLB = 32 * NF * 40;
    const int BUFH = 2 * GPLA + 2 * GPLB;
    const int tid = threadIdx.x;
    const int m0 = blockIdx.y * 128, n0 = blockIdx.x * (32 * NF);
    const int warp = tid >> 5, lane = tid & 31;
    const int g = lane >> 2, ctg = lane & 3;
    const int wm = (warp >> 2) * 64, wn = (warp & 3) * (NF * 8);
    const uint32_t sbase = (uint32_t)__cvta_generic_to_shared(smg);

    // ldmatrix per-lane source rows
    const int arow = wm + (lane & 7) + ((lane >> 3) & 1) * 8;   // + mf*16
    const int akc  = (lane >> 4) * 8;                           // + kk
    const int brow = wn + (lane & 7) + (lane >> 4) * 8;         // + pair*16
    const int bkc  = ((lane >> 3) & 1) * 8;                     // + kk

    float acc[4][NF][4];
#pragma unroll
    for (int a = 0; a < 4; a++)
#pragma unroll
        for (int b = 0; b < NF; b++)
#pragma unroll
            for (int c = 0; c < 4; c++) acc[a][b][c] = 0.f;

    const int nc = K / 32;
    g2_fill<NF>(Ah, Al, Bh, Bl, K, m0, n0, 0, sbase, 0, tid);
    CP_COMMIT();

    for (int c = 0; c < nc; c++) {
        if (c + 1 < nc) {
            g2_fill<NF>(Ah, Al, Bh, Bl, K, m0, n0, (c + 1) * 32, sbase, (c + 1) & 1, tid);
            CP_COMMIT();
            CP_WAIT(1);
        } else {
            CP_WAIT(0);
        }
        __syncthreads();

        const uint32_t bufb = sbase + (uint32_t)((c & 1) * BUFH * 2);
        const uint32_t Ahb = bufb;
        const uint32_t Alb = bufb + GPLA * 2;
        const uint32_t Bhb = bufb + 2 * GPLA * 2;
        const uint32_t Blb = Bhb + GPLB * 2;

#pragma unroll
        for (int kk = 0; kk < 32; kk += 16) {
            uint32_t ah[4][4], al[4][4], bh[NF][2], bl[NF][2];
#pragma unroll
            for (int mf = 0; mf < 4; mf++) {
                uint32_t ao = (uint32_t)(((arow + mf * 16) * 40 + kk + akc) * 2);
                LDSM_X4(ah[mf][0], ah[mf][1], ah[mf][2], ah[mf][3], Ahb + ao);
                LDSM_X4(al[mf][0], al[mf][1], al[mf][2], al[mf][3], Alb + ao);
            }
#pragma unroll
            for (int pr = 0; pr < NF / 2; pr++) {
                uint32_t bo = (uint32_t)(((brow + pr * 16) * 40 + kk + bkc) * 2);
                LDSM_X4(bh[2*pr][0], bh[2*pr][1], bh[2*pr+1][0], bh[2*pr+1][1], Bhb + bo);
                LDSM_X4(bl[2*pr][0], bl[2*pr][1], bl[2*pr+1][0], bl[2*pr+1][1], Blb + bo);
            }
#pragma unroll
            for (int mf = 0; mf < 4; mf++)
#pragma unroll
                for (int nf = 0; nf < NF; nf++) MMA_BF16(acc[mf][nf], ah[mf], bh[nf]);
#pragma unroll
            for (int mf = 0; mf < 4; mf++)
#pragma unroll
                for (int nf = 0; nf < NF; nf++) MMA_BF16(acc[mf][nf], ah[mf], bl[nf]);
#pragma unroll
            for (int mf = 0; mf < 4; mf++)
#pragma unroll
                for (int nf = 0; nf < NF; nf++) MMA_BF16(acc[mf][nf], al[mf], bh[nf]);
        }
        __syncthreads();
    }

#pragma unroll
    for (int mf = 0; mf < 4; mf++)
#pragma unroll
        for (int nf = 0; nf < NF; nf++) {
            int r  = m0 + wm + mf * 16 + g;
            int cl = n0 + wn + nf * 8 + 2 * ctg;
            *(float2*)&C[(size_t)r * N + cl]       = make_float2(acc[mf][nf][0], acc[mf][nf][1]);
            *(float2*)&C[(size_t)(r + 8) * N + cl] = make_float2(acc[mf][nf][2], acc[mf][nf][3]);
        }
}

#define G2_SMEM8 ((2*GPLA + 2*32*8*40) * 2 * 2)   // 122880 bytes
#define G2_SMEM4 ((2*GPLA + 2*32*4*40) * 2 * 2)   // 81920 bytes

// =====================================================================
// RoPE: Cq/Ck fp32 -> Qh/Ql (scaled by 1/sqrt(HD)) and Kh/Kl bf16.
// =====================================================================
__global__ __launch_bounds__(256)
void rope_qk_kernel(const float* __restrict__ Cq, const float* __restrict__ Ck,
                    __nv_bfloat16* __restrict__ Qh, __nv_bfloat16* __restrict__ Ql,
                    __nv_bfloat16* __restrict__ Kh, __nv_bfloat16* __restrict__ Kl)
{
    __shared__ float cs[64], sn[64];
    const int s = blockIdx.x, b = blockIdx.y;
    const int tid = threadIdx.x;
    const float sscale = 0.08838834764831845f;   // 1/sqrt(128)

    if (tid < 64) {
        double f = pow(10000.0, -(double)tid / 64.0);
        double a = (double)s * f;
        cs[tid] = (float)cos(a);
        sn[tid] = (float)sin(a);
    }
    __syncthreads();

    const float* cq = Cq + (size_t)(b * Ss + s) * (Hh * HD);
    for (int p = tid; p < Hh * 64; p += 256) {
        int u = p >> 6, i = p & 63;
        float x1 = cq[u * HD + i], x2 = cq[u * HD + i + 64];
        float c = cs[i], sv = sn[i];
        float y1 = (x1 * c - x2 * sv) * sscale;
        float y2 = (x2 * c + x1 * sv) * sscale;
        size_t dst = ((size_t)(b * Hh + u) * Ss + s) * HD;
        __nv_bfloat16 h1 = __float2bfloat16(y1), h2 = __float2bfloat16(y2);
        Qh[dst + i]      = h1;
        Qh[dst + i + 64] = h2;
        Ql[dst + i]      = __float2bfloat16(y1 - __bfloat162float(h1));
        Ql[dst + i + 64] = __float2bfloat16(y2 - __bfloat162float(h2));
    }

    const float* ck = Ck + (size_t)(b * Ss + s) * (KVh * HD);
    for (int p = tid; p < KVh * 64; p += 256) {
        int u = p >> 6, i = p & 63;
        float x1 = ck[u * HD + i], x2 = ck[u * HD + i + 64];
        float c = cs[i], sv = sn[i];
        float y1 = x1 * c - x2 * sv;
        float y2 = x2 * c + x1 * sv;
        size_t dst = ((size_t)(b * KVh + u) * Ss + s) * HD;
        __nv_bfloat16 h1 = __float2bfloat16(y1), h2 = __float2bfloat16(y2);
        Kh[dst + i]      = h1;
        Kh[dst + i + 64] = h2;
        Kl[dst + i]      = __float2bfloat16(y1 - __bfloat162float(h1));
        Kl[dst + i + 64] = __float2bfloat16(y2 - __bfloat162float(h2));
    }
}

// =====================================================================
// V transpose + split: Cv fp32 -> Vt (B,KV,HD,S) bf16 hi/lo
// =====================================================================
__global__ __launch_bounds__(256)
void transpose_v_kernel(const float* __restrict__ Cv,
                        __nv_bfloat16* __restrict__ Vth, __nv_bfloat16* __restrict__ Vtl)
{
    __shared__ float t[32][33];
    const int s0 = blockIdx.x * 32, d0 = blockIdx.y * 32;
    const int bkv = blockIdx.z;
    const int b = bkv >> 2, kv = bkv & 3;
    const int tx = threadIdx.x, ty = threadIdx.y;   // 32 x 8

#pragma unroll
    for (int i = 0; i < 32; i += 8)
        t[ty + i][tx] = Cv[(size_t)(b * Ss + s0 + ty + i) * (KVh * HD) + kv * HD + d0 + tx];
    __syncthreads();
#pragma unroll
    for (int i = 0; i < 32; i += 8) {
        float x = t[tx][ty + i];
        __nv_bfloat16 h = __float2bfloat16(x);
        size_t o = ((size_t)(b * KVh + kv) * HD + d0 + ty + i) * Ss + s0 + tx;
        Vth[o] = h;
        Vtl[o] = __float2bfloat16(x - __bfloat162float(h));
    }
}

// =====================================================================
// Flash attention on tensor cores (mma.sync bf16x3, causal, GQA).
// BQ=128, BK=64. 8 warps; Q in registers; double-buffered cp.async.
// =====================================================================
#define KPL  8704            // 64*136 halves
#define VPL  9216            // 128*72 halves
#define ABUF (2*KPL + 2*VPL) // 35840 halves per buffer
#define ATTN_SMEM (2*ABUF*2) // 143360 bytes

__device__ __forceinline__ void attn_fill(
    const __nv_bfloat16* Khg, const __nv_bfloat16* Klg,
    const __nv_bfloat16* Vthg, const __nv_bfloat16* Vtlg,
    int kt, uint32_t sbase, int buf, int tid)
{
    uint32_t b0 = sbase + (uint32_t)(buf * ABUF * 2);
#pragma unroll
    for (int j = 0; j < 16; j++) {
        int e = tid + j * 256;
        if (e < 2048) {                     // K hi/lo: 64 rows x 16 chunks
            int part = e >> 10, idx = e & 1023;
            int row = idx >> 4, ch = idx & 15;
            const __nv_bfloat16* g = (part ? Klg : Khg) +
                (size_t)(kt * 64 + row) * HD + ch * 8;
            CP_ASYNC16(b0 + (uint32_t)((part * KPL + row * 136 + ch * 8) * 2), g);
        } else {                            // Vt hi/lo: 128 rows x 8 chunks
            int e2 = e - 2048;
            int part = e2 >> 10, idx = e2 & 1023;
            int row = idx >> 3, ch = idx & 7;
            const __nv_bfloat16* g = (part ? Vtlg : Vthg) +
                (size_t)row * Ss + kt * 64 + ch * 8;
            CP_ASYNC16(b0 + (uint32_t)((2 * KPL + part * VPL + row * 72 + ch * 8) * 2), g);
        }
    }
}

__global__ __launch_bounds__(256, 1)
void attn_mma_kernel(const __nv_bfloat16* __restrict__ Qh, const __nv_bfloat16* __restrict__ Ql,
                     const __nv_bfloat16* __restrict__ Khg, const __nv_bfloat16* __restrict__ Klg,
                     const __nv_bfloat16* __restrict__ Vthg, const __nv_bfloat16* __restrict__ Vtlg,
                     __nv_bfloat16* __restrict__ Ath, __nv_bfloat16* __restrict__ Atl)
{
    extern __shared__ __nv_bfloat16 sma[];
    const int qt = (int)gridDim.x - 1 - (int)blockIdx.x;   // reversed for balance
    const int u = blockIdx.y, b = blockIdx.z;
    const int tid = threadIdx.x;
    const int wid = tid >> 5, lane = tid & 31;
    const int g = lane >> 2, ctg = lane & 3;
    const uint32_t sbase = (uint32_t)__cvta_generic_to_shared(sma);

    const __nv_bfloat16* Kg  = Khg  + (size_t)(b * KVh + (u >> 2)) * Ss * HD;
    const __nv_bfloat16* Klg2= Klg  + (size_t)(b * KVh + (u >> 2)) * Ss * HD;
    const __nv_bfloat16* Vhg = Vthg + (size_t)(b * KVh + (u >> 2)) * HD * Ss;
    const __nv_bfloat16* Vlg = Vtlg + (size_t)(b * KVh + (u >> 2)) * HD * Ss;

    uint32_t qh[8][4], ql[8][4];
    {
        const __nv_bfloat16* Qbase_h = Qh + ((size_t)(b * Hh + u) * Ss + qt * 128 + wid * 16) * HD;
        const __nv_bfloat16* Qbase_l = Ql + ((size_t)(b * Hh + u) * Ss + qt * 128 + wid * 16) * HD;
#pragma unroll
        for (int ks = 0; ks < 8; ks++) {
            int klo = ks * 16 + 2 * ctg;
            qh[ks][0] = *(const uint32_t*)&Qbase_h[(size_t)g * HD + klo];
            qh[ks][1] = *(const uint32_t*)&Qbase_h[(size_t)(g + 8) * HD + klo];
            qh[ks][2] = *(const uint32_t*)&Qbase_h[(size_t)g * HD + klo + 8];
            qh[ks][3] = *(const uint32_t*)&Qbase_h[(size_t)(g + 8) * HD + klo + 8];
            ql[ks][0] = *(const uint32_t*)&Qbase_l[(size_t)g * HD + klo];
            ql[ks][1] = *(const uint32_t*)&Qbase_l[(size_t)(g + 8) * HD + klo];
            ql[ks][2] = *(const uint32_t*)&Qbase_l[(size_t)g * HD + klo + 8];
            ql[ks][3] = *(const uint32_t*)&Qbase_l[(size_t)(g + 8) * HD + klo + 8];
        }
    }

    float o[16][4];
#pragma unroll
    for (int nf = 0; nf < 16; nf++)
#pragma unroll
        for (int c = 0; c < 4; c++) o[nf][c] = 0.f;
    float m0 = -1e30f, m1 = -1e30f, l0 = 0.f, l1 = 0.f;

    const int row0 = qt * 128 + wid * 16 + g;
    const int row1 = row0 + 8;
    const int nkt = 2 * qt + 2;

    attn_fill(Kg, Klg2, Vhg, Vlg, 0, sbase, 0, tid);
    CP_COMMIT();

    for (int kt = 0; kt < nkt; kt++) {
        if (kt + 1 < nkt) {
            attn_fill(Kg, Klg2, Vhg, Vlg, kt + 1, sbase, (kt + 1) & 1, tid);
            CP_COMMIT();
            CP_WAIT(1);
        } else {
            CP_WAIT(0);
        }
        __syncthreads();

        const int buf = kt & 1;
        const __nv_bfloat16* Khs = sma + buf * ABUF;
        const __nv_bfloat16* Kls = Khs + KPL;
        const __nv_bfloat16* Vhs = Khs + 2 * KPL;
        const __nv_bfloat16* Vls = Vhs + VPL;

        float sf[8][4];
#pragma unroll
        for (int nf = 0; nf < 8; nf++)
#pragma unroll
            for (int c = 0; c < 4; c++) sf[nf][c] = 0.f;

#pragma unroll
        for (int ks = 0; ks < 8; ks++) {
#pragma unroll
            for (int nf = 0; nf < 8; nf++) {
                int so = (nf * 8 + g) * 136 + ks * 16 + 2 * ctg;
                uint32_t bh[2], bl[2];
                bh[0] = *(const uint32_t*)&Khs[so];
                bh[1] = *(const uint32_t*)&Khs[so + 8];
                bl[0] = *(const uint32_t*)&Kls[so];
                bl[1] = *(const uint32_t*)&Kls[so + 8];
                MMA_BF16(sf[nf], qh[ks], bh);
                MMA_BF16(sf[nf], ql[ks], bh);
                MMA_BF16(sf[nf], qh[ks], bl);
            }
        }

        if (kt >= 2 * qt) {
            const int colb = kt * 64 + 2 * ctg;
#pragma unroll
            for (int nf = 0; nf < 8; nf++) {
                int c0 = colb + nf * 8;
                if (c0     > row0) sf[nf][0] = -1e30f;
                if (c0 + 1 > row0) sf[nf][1] = -1e30f;
                if (c0     > row1) sf[nf][2] = -1e30f;
                if (c0 + 1 > row1) sf[nf][3] = -1e30f;
            }
        }

        float mx0 = m0, mx1 = m1;
#pragma unroll
        for (int nf = 0; nf < 8; nf++) {
            mx0 = fmaxf(mx0, fmaxf(sf[nf][0], sf[nf][1]));
            mx1 = fmaxf(mx1, fmaxf(sf[nf][2], sf[nf][3]));
        }
        mx0 = fmaxf(mx0, __shfl_xor_sync(0xffffffffu, mx0, 1));
        mx0 = fmaxf(mx0, __shfl_xor_sync(0xffffffffu, mx0, 2));
        mx1 = fmaxf(mx1, __shfl_xor_sync(0xffffffffu, mx1, 1));
        mx1 = fmaxf(mx1, __shfl_xor_sync(0xffffffffu, mx1, 2));

        float a0 = __expf(m0 - mx0), a1 = __expf(m1 - mx1);
        m0 = mx0; m1 = mx1;

        float s0 = 0.f, s1 = 0.f;
#pragma unroll
        for (int nf = 0; nf < 8; nf++) {
            sf[nf][0] = __expf(sf[nf][0] - mx0);
            sf[nf][1] = __expf(sf[nf][1] - mx0);
            sf[nf][2] = __expf(sf[nf][2] - mx1);
            sf[nf][3] = __expf(sf[nf][3] - mx1);
            s0 += sf[nf][0] + sf[nf][1];
            s1 += sf[nf][2] + sf[nf][3];
        }
        s0 += __shfl_xor_sync(0xffffffffu, s0, 1);
        s0 += __shfl_xor_sync(0xffffffffu, s0, 2);
        s1 += __shfl_xor_sync(0xffffffffu, s1, 1);
        s1 += __shfl_xor_sync(0xffffffffu, s1, 2);
        l0 = l0 * a0 + s0;
        l1 = l1 * a1 + s1;

#pragma unroll
        for (int nf = 0; nf < 16; nf++) {
            o[nf][0] *= a0; o[nf][1] *= a0;
            o[nf][2] *= a1; o[nf][3] *= a1;
        }

        uint32_t ph[4][4], pl[4][4];
#pragma unroll
        for (int ks = 0; ks < 4; ks++) {
            pkhl(ph[ks][0], pl[ks][0], sf[2*ks][0],   sf[2*ks][1]);
            pkhl(ph[ks][1], pl[ks][1], sf[2*ks][2],   sf[2*ks][3]);
            pkhl(ph[ks][2], pl[ks][2], sf[2*ks+1][0], sf[2*ks+1][1]);
            pkhl(ph[ks][3], pl[ks][3], sf[2*ks+1][2], sf[2*ks+1][3]);
        }

#pragma unroll
        for (int ks = 0; ks < 4; ks++) {
#pragma unroll
            for (int nf = 0; nf < 16; nf++) {
                int vo = (nf * 8 + g) * 72 + ks * 16 + 2 * ctg;
                uint32_t vh[2], vl[2];
                vh[0] = *(const uint32_t*)&Vhs[vo];
                vh[1] = *(const uint32_t*)&Vhs[vo + 8];
                vl[0] = *(const uint32_t*)&Vls[vo];
                vl[1] = *(const uint32_t*)&Vls[vo + 8];
                MMA_BF16(o[nf], ph[ks], vh);
                MMA_BF16(o[nf], pl[ks], vh);
                MMA_BF16(o[nf], ph[ks], vl);
            }
        }
        __syncthreads();
    }

    const float inv0 = 1.f / l0, inv1 = 1.f / l1;
    const size_t rg0 = (size_t)(b * Ss + qt * 128 + wid * 16 + g) * 2048;
    const size_t rg1 = rg0 + 8 * 2048;
#pragma unroll
    for (int nf = 0; nf < 16; nf++) {
        int col = u * 128 + nf * 8 + 2 * ctg;
        uint32_t h, l;
        pkhl(h, l, o[nf][0] * inv0, o[nf][1] * inv0);
        *(uint32_t*)&Ath[rg0 + col] = h;
        *(uint32_t*)&Atl[rg0 + col] = l;
        pkhl(h, l, o[nf][2] * inv1, o[nf][3] * inv1);
        *(uint32_t*)&Ath[rg1 + col] = h;
        *(uint32_t*)&Atl[rg1 + col] = l;
    }
}

// =====================================================================
// launch
// =====================================================================
extern "C" void kernel_launch(void* const* d_in, const int* in_sizes, int n_in,
                              void* d_out, int out_size)
{
    const float *X = 0, *Wq = 0, *Wk = 0, *Wv = 0, *Wo = 0;
    int seen_big = 0, seen_mid = 0, seen_small = 0;
    for (int i = 0; i < n_in; i++) {
        long sz = in_sizes[i];
        if (sz == 8388608) {
            if (seen_big == 0) X = (const float*)d_in[i];
            seen_big++;
        } else if (sz == 4194304) {
            if (seen_mid == 0) Wq = (const float*)d_in[i];
            else               Wo = (const float*)d_in[i];
            seen_mid++;
        } else if (sz == 1048576) {
            if (seen_small == 0) Wk = (const float*)d_in[i];
            else                 Wv = (const float*)d_in[i];
            seen_small++;
        }
    }
    if (!X || !Wq || !Wk || !Wv || !Wo) {
        X  = (const float*)d_in[0];
        Wq = (const float*)d_in[2];
        Wk = (const float*)d_in[3];
        Wv = (const float*)d_in[4];
        Wo = (const float*)d_in[5];
    }
    float* out = (float*)d_out;

    float *Cq, *Ck, *Cv;
    __nv_bfloat16 *Xh, *Xl, *Ath, *Atl, *Wqh, *Wql, *Wkh, *Wkl, *Wvh, *Wvl, *Woh, *Wol;
    __nv_bfloat16 *Qh, *Ql, *Kh, *Kl, *Vth, *Vtl;
    cudaGetSymbolAddress((void**)&Cq,   g_Cq);
    cudaGetSymbolAddress((void**)&Ck,   g_Ck);
    cudaGetSymbolAddress((void**)&Cv,   g_Cv);
    cudaGetSymbolAddress((void**)&Xh,  g_Xh);   cudaGetSymbolAddress((void**)&Xl,  g_Xl);
    cudaGetSymbolAddress((void**)&Ath, g_Ath);  cudaGetSymbolAddress((void**)&Atl, g_Atl);
    cudaGetSymbolAddress((void**)&Wqh, g_Wqh);  cudaGetSymbolAddress((void**)&Wql, g_Wql);
    cudaGetSymbolAddress((void**)&Wkh, g_Wkh);  cudaGetSymbolAddress((void**)&Wkl, g_Wkl);
    cudaGetSymbolAddress((void**)&Wvh, g_Wvh);  cudaGetSymbolAddress((void**)&Wvl, g_Wvl);
    cudaGetSymbolAddress((void**)&Woh, g_Woh);  cudaGetSymbolAddress((void**)&Wol, g_Wol);
    cudaGetSymbolAddress((void**)&Qh,  g_Qh);   cudaGetSymbolAddress((void**)&Ql,  g_Ql);
    cudaGetSymbolAddress((void**)&Kh,  g_Kh);   cudaGetSymbolAddress((void**)&Kl,  g_Kl);
    cudaGetSymbolAddress((void**)&Vth, g_Vth);  cudaGetSymbolAddress((void**)&Vtl, g_Vtl);

    cudaFuncSetAttribute(gemm2<8>,       cudaFuncAttributeMaxDynamicSharedMemorySize, G2_SMEM8);
    cudaFuncSetAttribute(gemm2<4>,       cudaFuncAttributeMaxDynamicSharedMemorySize, G2_SMEM4);
    cudaFuncSetAttribute(attn_mma_kernel,cudaFuncAttributeMaxDynamicSharedMemorySize, ATTN_SMEM);

    // operand prep
    split_kernel <<<(Mrows * Dd / 4 + 255) / 256, 256>>>(X, Xh, Xl, Mrows * Dd / 4);
    split_t_kernel<<<dim3(2048 / 32, 2048 / 32), dim3(32, 8)>>>(Wq, Wqh, Wql, 2048, 2048);
    split_t_kernel<<<dim3(512 / 32,  2048 / 32), dim3(32, 8)>>>(Wk, Wkh, Wkl, 2048, 512);
    split_t_kernel<<<dim3(512 / 32,  2048 / 32), dim3(32, 8)>>>(Wv, Wvh, Wvl, 2048, 512);
    split_t_kernel<<<dim3(2048 / 32, 2048 / 32), dim3(32, 8)>>>(Wo, Woh, Wol, 2048, 2048);

    // QKV projections (mma.sync + ldmatrix)
    gemm2<8><<<dim3(2048 / 256, Mrows / 128), 256, G2_SMEM8>>>(Xh, Xl, Wqh, Wql, Cq, Mrows, 2048, 2048);
    gemm2<4><<<dim3(512 / 128,  Mrows / 128), 256, G2_SMEM4>>>(Xh, Xl, Wkh, Wkl, Ck, Mrows, 512, 2048);
    gemm2<4><<<dim3(512 / 128,  Mrows / 128), 256, G2_SMEM4>>>(Xh, Xl, Wvh, Wvl, Cv, Mrows, 512, 2048);

    // RoPE + layout + splits for attention
    rope_qk_kernel<<<dim3(Ss, Bb), 256>>>(Cq, Ck, Qh, Ql, Kh, Kl);
    transpose_v_kernel<<<dim3(Ss / 32, HD / 32, Bb * KVh), dim3(32, 8)>>>(Cv, Vth, Vtl);

    // Flash attention (mma.sync bf16x3)
    attn_mma_kernel<<<dim3(Ss / 128, Hh, Bb), 256, ATTN_SMEM>>>(Qh, Ql, Kh, Kl, Vth, Vtl, Ath, Atl);

    // Output projection
    gemm2<8><<<dim3(2048 / 256, Mrows / 128), 256, G2_SMEM8>>>(Ath, Atl, Woh, Wol, out, Mrows, 2048, 2048);
}